// round 3
// baseline (speedup 1.0000x reference)
#include <cuda_runtime.h>
#include <cuda_bf16.h>
#include <cuda_pipeline.h>
#include <mma.h>
#include <cstdint>

using namespace nvcuda;

#define NN 100000
#define EE 1600000
#define MPAD 100096   // 782 * 128

// ---------------- scratch ----------------
__device__ int   g_counts[NN];
__device__ int   g_row[NN + 1];
__device__ int   g_cursor[NN];
__device__ float g_dinv[NN];
__device__ int   g_csrc[EE];

__device__ float          g_h[(size_t)MPAD * 128];     // GEMM fp32 out (agg input)
__device__ float          g_hb[(size_t)MPAD * 128];    // layer2 agg fp32 out
__device__ float          g_c16[(size_t)MPAD * 16];    // layer3 gemm out
__device__ __nv_bfloat16  g_xp[(size_t)MPAD * 768];    // packed x:  [xh | xl | xh]
__device__ __nv_bfloat16  g_ap[(size_t)MPAD * 384];    // packed h1: [hh | hl | hh]
__device__ __nv_bfloat16  g_w1p[768 * 128];            // [W1h ; W1h ; W1l]
__device__ __nv_bfloat16  g_w2p[384 * 128];            // [W2h ; W2h ; W2l]

// ---------------- helpers ----------------
__device__ __forceinline__ void split4(float4 v, uint2& hi, uint2& lo) {
    __align__(8) __nv_bfloat16 h[4], l[4];
    float f[4] = {v.x, v.y, v.z, v.w};
#pragma unroll
    for (int i = 0; i < 4; i++) {
        h[i] = __float2bfloat16_rn(f[i]);
        l[i] = __float2bfloat16_rn(f[i] - __bfloat162float(h[i]));
    }
    hi = *(uint2*)h;
    lo = *(uint2*)l;
}

// x[M,256] -> XP[M,768] = [xh | xl | xh]
__global__ void k_split_x(const float* __restrict__ x, __nv_bfloat16* __restrict__ XP) {
    int i = blockIdx.x * blockDim.x + threadIdx.x;
    if (i >= NN * 64) return;                 // 64 float4 per row
    int row = i >> 6, c4 = (i & 63) * 4;
    float4 v = ((const float4*)x)[i];
    uint2 h, l; split4(v, h, l);
    __nv_bfloat16* base = XP + (size_t)row * 768;
    *(uint2*)(base + c4)        = h;
    *(uint2*)(base + 256 + c4)  = l;
    *(uint2*)(base + 512 + c4)  = h;
}

// W[K,128] -> WP[3K,128] = [Wh ; Wh ; Wl]
__global__ void k_split_w(const float* __restrict__ W, __nv_bfloat16* __restrict__ WP, int K) {
    int i = blockIdx.x * blockDim.x + threadIdx.x;
    if (i >= K * 32) return;                  // 32 float4 per row
    int row = i >> 5, c4 = (i & 31) * 4;
    float4 v = ((const float4*)W)[i];
    uint2 h, l; split4(v, h, l);
    *(uint2*)(WP + (size_t)row * 128 + c4)           = h;
    *(uint2*)(WP + (size_t)(K + row) * 128 + c4)     = h;
    *(uint2*)(WP + (size_t)(2 * K + row) * 128 + c4) = l;
}

// ---------------- CSR build ----------------
__global__ void k_zero_counts() {
    int i = blockIdx.x * blockDim.x + threadIdx.x;
    if (i < NN) g_counts[i] = 0;
}

__global__ void k_hist(const int* __restrict__ dst) {
    int e = blockIdx.x * blockDim.x + threadIdx.x;
    if (e < EE) atomicAdd(&g_counts[dst[e]], 1);
}

__global__ void k_scan() {
    __shared__ int part[1024];
    const int CH = (NN + 1023) / 1024;
    int t = threadIdx.x;
    int beg = t * CH;
    int end = beg + CH; if (end > NN) end = NN;
    int s = 0;
    for (int i = beg; i < end; i++) s += g_counts[i];
    part[t] = s;
    __syncthreads();
    for (int off = 1; off < 1024; off <<= 1) {
        int v = (t >= off) ? part[t - off] : 0;
        __syncthreads();
        part[t] += v;
        __syncthreads();
    }
    int run = (t == 0) ? 0 : part[t - 1];
    for (int i = beg; i < end; i++) {
        int c = g_counts[i];
        g_row[i] = run;
        g_cursor[i] = run;
        g_dinv[i] = rsqrtf((float)(c + 1));
        run += c;
    }
    if (t == 1023) g_row[NN] = part[1023];
}

__global__ void k_scatter(const int* __restrict__ src, const int* __restrict__ dst) {
    int e = blockIdx.x * blockDim.x + threadIdx.x;
    if (e < EE) {
        int d = dst[e];
        int p = atomicAdd(&g_cursor[d], 1);
        g_csrc[p] = src[e];
    }
}

// ---------------- packed bf16 GEMM: C[MPAD,128] = A[MPAD,KP] * B[KP,128] ----------------
// Double-buffered cp.async, BM=BN=128, BK=32, 8 warps (32x64 warp tiles).
template <int KP>
__global__ __launch_bounds__(256) void pgemm128(
    const __nv_bfloat16* __restrict__ A, const __nv_bfloat16* __restrict__ B,
    float* __restrict__ C)
{
    constexpr int BM = 128, BK = 32;
    constexpr int LDA = BK + 8;    // 40 elems (80B, 16B-mult)
    constexpr int LDB = 128 + 8;   // 136 elems (272B, 16B-mult)
    constexpr int T = KP / BK;

    __shared__ __align__(16) __nv_bfloat16 sA[2][BM * LDA];
    __shared__ __align__(16) __nv_bfloat16 sB[2][BK * LDB];

    int tid  = threadIdx.x;
    int warp = tid >> 5;
    int wm   = warp >> 1;    // 0..3 -> 32-row slab
    int wn   = warp & 1;     // 0..1 -> 64-col slab
    size_t rowBase = (size_t)blockIdx.x * BM;

    // per-thread load coords (16B chunks)
    int aR = tid >> 1;              // 0..127
    int aC = (tid & 1) * 16;        // 0 or 16 (two chunks per row pair? -> each thread does 2 chunks)
    int bR = tid >> 3;              // 0..31
    int bC = (tid & 7) * 16;        // 0..112

    auto loadStage = [&](int st, int k0) {
        // A: 128 x 32 bf16 = 512 x 16B chunks, 2 per thread
#pragma unroll
        for (int rep = 0; rep < 2; rep++) {
            int r = aR, c = aC + rep * 8 * 0;  // placeholder (adjusted below)
            (void)r; (void)c;
        }
        // chunk i in [0,512): r = i>>2, c8 = (i&3)*8
#pragma unroll
        for (int i = tid; i < 512; i += 256) {
            int r = i >> 2, c8 = (i & 3) * 8;
            __pipeline_memcpy_async(&sA[st][r * LDA + c8],
                                    &A[(rowBase + r) * KP + k0 + c8], 16);
        }
        // B: 32 x 128 bf16 = 512 x 16B chunks
#pragma unroll
        for (int i = tid; i < 512; i += 256) {
            int r = i >> 4, c8 = (i & 15) * 8;
            __pipeline_memcpy_async(&sB[st][r * LDB + c8],
                                    &B[(size_t)(k0 + r) * 128 + c8], 16);
        }
    };
    (void)aR; (void)aC; (void)bR; (void)bC;

    wmma::fragment<wmma::accumulator, 16, 16, 16, float> acc[2][4];
#pragma unroll
    for (int i = 0; i < 2; i++)
#pragma unroll
        for (int j = 0; j < 4; j++) wmma::fill_fragment(acc[i][j], 0.f);

    loadStage(0, 0);
    __pipeline_commit();

    for (int t = 0; t < T; t++) {
        int cur = t & 1;
        if (t + 1 < T) loadStage((t + 1) & 1, (t + 1) * BK);
        __pipeline_commit();
        __pipeline_wait_prior(1);
        __syncthreads();

#pragma unroll
        for (int kk = 0; kk < BK; kk += 16) {
            wmma::fragment<wmma::matrix_a, 16, 16, 16, __nv_bfloat16, wmma::row_major> af[2];
#pragma unroll
            for (int i = 0; i < 2; i++)
                wmma::load_matrix_sync(af[i], &sA[cur][(wm * 32 + i * 16) * LDA + kk], LDA);
#pragma unroll
            for (int j = 0; j < 4; j++) {
                wmma::fragment<wmma::matrix_b, 16, 16, 16, __nv_bfloat16, wmma::row_major> bf;
                wmma::load_matrix_sync(bf, &sB[cur][kk * LDB + wn * 64 + j * 16], LDB);
                wmma::mma_sync(acc[0][j], af[0], bf, acc[0][j]);
                wmma::mma_sync(acc[1][j], af[1], bf, acc[1][j]);
            }
        }
        __syncthreads();
    }

#pragma unroll
    for (int i = 0; i < 2; i++)
#pragma unroll
        for (int j = 0; j < 4; j++) {
            size_t r = rowBase + wm * 32 + i * 16;
            int c = wn * 64 + j * 16;
            wmma::store_matrix_sync(&C[r * 128 + c], acc[i][j], 128, wmma::mem_row_major);
        }
}

// ---------------- small GEMM: C[M,16] = A[M,128] * W[128,16] ----------------
__global__ __launch_bounds__(256) void gemm16(
    const float* __restrict__ A, const float* __restrict__ W,
    float* __restrict__ C, int M)
{
    __shared__ float xs[64][132];
    __shared__ float ws[128][16];

    int tid = threadIdx.x;
    int r0 = blockIdx.x * 64;

    for (int i = tid; i < 2048; i += 256) {
        int row = i >> 5;
        int c4 = i & 31;
        int gr = r0 + row;
        float4 v = (gr < M) ? *(const float4*)(A + (size_t)gr * 128 + c4 * 4)
                            : make_float4(0.f, 0.f, 0.f, 0.f);
        *(float4*)(&xs[row][c4 * 4]) = v;
    }
    for (int i = tid; i < 2048; i += 256) ws[i >> 4][i & 15] = W[i];
    __syncthreads();

    int col = tid & 15;
    int rq  = tid >> 4;
    float acc[4] = {0.f, 0.f, 0.f, 0.f};
    for (int k = 0; k < 128; k++) {
        float w = ws[k][col];
#pragma unroll
        for (int r = 0; r < 4; r++)
            acc[r] = fmaf(xs[rq * 4 + r][k], w, acc[r]);
    }
#pragma unroll
    for (int r = 0; r < 4; r++) {
        int gr = r0 + rq * 4 + r;
        if (gr < M) C[(size_t)gr * 16 + col] = acc[r];
    }
}

// ---------------- aggregation, F=128 ----------------
// SPLIT_OUT: write packed bf16 [hi | lo | hi] rows (stride 384) for next GEMM; else fp32.
template <bool RELU, bool SPLIT_OUT>
__global__ __launch_bounds__(256) void agg128(
    const float4* __restrict__ h, const float* __restrict__ bias,
    float4* __restrict__ outF, __nv_bfloat16* __restrict__ outP)
{
    int warp = (blockIdx.x * blockDim.x + threadIdx.x) >> 5;
    int lane = threadIdx.x & 31;
    if (warp >= NN) return;
    int v = warp;

    float dv = g_dinv[v];
    float4 self = h[(size_t)v * 32 + lane];
    float4 acc;
    acc.x = dv * self.x; acc.y = dv * self.y;
    acc.z = dv * self.z; acc.w = dv * self.w;

    int rs = g_row[v], re = g_row[v + 1];
    int base = rs;
    for (; base + 32 <= re; base += 32) {
        int   s = g_csrc[base + lane];
        float d = g_dinv[s];
#pragma unroll
        for (int j = 0; j < 32; j++) {
            int   sj = __shfl_sync(0xffffffffu, s, j);
            float dj = __shfl_sync(0xffffffffu, d, j);
            float4 hv = h[(size_t)sj * 32 + lane];
            acc.x = fmaf(dj, hv.x, acc.x);
            acc.y = fmaf(dj, hv.y, acc.y);
            acc.z = fmaf(dj, hv.z, acc.z);
            acc.w = fmaf(dj, hv.w, acc.w);
        }
    }
    if (base < re) {
        int cnt = re - base;
        int   s = (lane < cnt) ? g_csrc[base + lane] : 0;
        float d = (lane < cnt) ? g_dinv[s] : 0.f;
        for (int j = 0; j < cnt; j++) {
            int   sj = __shfl_sync(0xffffffffu, s, j);
            float dj = __shfl_sync(0xffffffffu, d, j);
            float4 hv = h[(size_t)sj * 32 + lane];
            acc.x = fmaf(dj, hv.x, acc.x);
            acc.y = fmaf(dj, hv.y, acc.y);
            acc.z = fmaf(dj, hv.z, acc.z);
            acc.w = fmaf(dj, hv.w, acc.w);
        }
    }

    float4 bb = *(const float4*)(bias + 4 * lane);
    acc.x = fmaf(acc.x, dv, bb.x);
    acc.y = fmaf(acc.y, dv, bb.y);
    acc.z = fmaf(acc.z, dv, bb.z);
    acc.w = fmaf(acc.w, dv, bb.w);
    if (RELU) {
        acc.x = fmaxf(acc.x, 0.f); acc.y = fmaxf(acc.y, 0.f);
        acc.z = fmaxf(acc.z, 0.f); acc.w = fmaxf(acc.w, 0.f);
    }
    if (SPLIT_OUT) {
        uint2 hi, lo;
        split4(acc, hi, lo);
        __nv_bfloat16* rowp = outP + (size_t)v * 384 + 4 * lane;
        *(uint2*)(rowp)       = hi;
        *(uint2*)(rowp + 128) = lo;
        *(uint2*)(rowp + 256) = hi;
    } else {
        outF[(size_t)v * 32 + lane] = acc;
    }
}

// ---------------- aggregation, F=16 ----------------
__global__ __launch_bounds__(256) void agg16(
    const float* __restrict__ h, const float* __restrict__ bias,
    float* __restrict__ out)
{
    int warp = (blockIdx.x * blockDim.x + threadIdx.x) >> 5;
    int lane = threadIdx.x & 31;
    if (warp >= NN) return;
    int v = warp;

    float dv = g_dinv[v];
    float acc = (lane < 16) ? dv * h[(size_t)v * 16 + lane] : 0.f;

    int rs = g_row[v], re = g_row[v + 1];
    int base = rs;
    for (; base + 32 <= re; base += 32) {
        int   s = g_csrc[base + lane];
        float d = g_dinv[s];
#pragma unroll
        for (int j = 0; j < 32; j++) {
            int   sj = __shfl_sync(0xffffffffu, s, j);
            float dj = __shfl_sync(0xffffffffu, d, j);
            if (lane < 16) acc = fmaf(dj, h[(size_t)sj * 16 + lane], acc);
        }
    }
    if (base < re) {
        int cnt = re - base;
        int   s = (lane < cnt) ? g_csrc[base + lane] : 0;
        float d = (lane < cnt) ? g_dinv[s] : 0.f;
        for (int j = 0; j < cnt; j++) {
            int   sj = __shfl_sync(0xffffffffu, s, j);
            float dj = __shfl_sync(0xffffffffu, d, j);
            if (lane < 16) acc = fmaf(dj, h[(size_t)sj * 16 + lane], acc);
        }
    }

    if (lane < 16) {
        acc = fmaf(acc, dv, bias[lane]);
        out[(size_t)v * 16 + lane] = acc;
    }
}

// ---------------- launch ----------------
extern "C" void kernel_launch(void* const* d_in, const int* in_sizes, int n_in,
                              void* d_out, int out_size)
{
    const float* x  = (const float*)d_in[0];
    const int*   ei = (const int*)d_in[1];
    const float* W1 = (const float*)d_in[2];
    const float* b1 = (const float*)d_in[3];
    const float* W2 = (const float*)d_in[4];
    const float* b2 = (const float*)d_in[5];
    const float* W3 = (const float*)d_in[6];
    const float* b3 = (const float*)d_in[7];
    float* out = (float*)d_out;

    float *pH, *pHB, *pC16;
    __nv_bfloat16 *pXP, *pAP, *pW1P, *pW2P;
    cudaGetSymbolAddress((void**)&pH,   g_h);
    cudaGetSymbolAddress((void**)&pHB,  g_hb);
    cudaGetSymbolAddress((void**)&pC16, g_c16);
    cudaGetSymbolAddress((void**)&pXP,  g_xp);
    cudaGetSymbolAddress((void**)&pAP,  g_ap);
    cudaGetSymbolAddress((void**)&pW1P, g_w1p);
    cudaGetSymbolAddress((void**)&pW2P, g_w2p);

    const int* e_src = ei;
    const int* e_dst = ei + EE;

    // CSR build
    k_zero_counts<<<(NN + 255) / 256, 256>>>();
    k_hist<<<(EE + 255) / 256, 256>>>(e_dst);
    k_scan<<<1, 1024>>>();
    k_scatter<<<(EE + 255) / 256, 256>>>(e_src, e_dst);

    // packed splits
    k_split_x<<<(NN * 64 + 255) / 256, 256>>>(x, pXP);
    k_split_w<<<(256 * 32 + 255) / 256, 256>>>(W1, pW1P, 256);
    k_split_w<<<(128 * 32 + 255) / 256, 256>>>(W2, pW2P, 128);

    const int AGG_BLOCKS = (NN + 7) / 8;
    const int GEMM_BLOCKS = MPAD / 128;  // 782

    // Layer 1
    pgemm128<768><<<GEMM_BLOCKS, 256>>>(pXP, pW1P, pH);
    agg128<true, true><<<AGG_BLOCKS, 256>>>((const float4*)pH, b1, nullptr, pAP);

    // Layer 2
    pgemm128<384><<<GEMM_BLOCKS, 256>>>(pAP, pW2P, pH);
    agg128<true, false><<<AGG_BLOCKS, 256>>>((const float4*)pH, b2, (float4*)pHB, nullptr);

    // Layer 3
    gemm16<<<(NN + 63) / 64, 256>>>(pHB, W3, pC16, NN);
    agg16<<<AGG_BLOCKS, 256>>>(pC16, b3, out);
}

// round 4
// speedup vs baseline: 1.5947x; 1.5947x over previous
#include <cuda_runtime.h>
#include <cuda_bf16.h>
#include <cuda_pipeline.h>
#include <mma.h>
#include <cstdint>

using namespace nvcuda;

#define NN 100000
#define EE 1600000
#define MPAD 100096   // 782 * 128
#define NBLK 391      // ceil(NN/256)

// ---------------- scratch ----------------
__device__ int   g_counts[NN];
__device__ int   g_bsum[NBLK];
__device__ int   g_boff[NBLK];
__device__ int   g_row[NN + 1];
__device__ int   g_cursor[NN];
__device__ float g_dinv[NN];
__device__ int   g_csrc[EE];

__device__ float          g_h[(size_t)MPAD * 128];   // GEMM out (agg input)
__device__ float          g_hb[(size_t)MPAD * 128];  // agg out (next GEMM input)
__device__ float          g_c16[(size_t)MPAD * 16];
__device__ __nv_bfloat16  g_w1p[512 * 128];          // [W1h ; W1l]
__device__ __nv_bfloat16  g_w2p[256 * 128];          // [W2h ; W2l]

// ---------------- helpers ----------------
__device__ __forceinline__ void split4(float4 v, uint2& hi, uint2& lo) {
    __align__(8) __nv_bfloat16 h[4], l[4];
    float f[4] = {v.x, v.y, v.z, v.w};
#pragma unroll
    for (int i = 0; i < 4; i++) {
        h[i] = __float2bfloat16_rn(f[i]);
        l[i] = __float2bfloat16_rn(f[i] - __bfloat162float(h[i]));
    }
    hi = *(uint2*)h;
    lo = *(uint2*)l;
}

// W[K,128] -> WP[2K,128] = [Wh ; Wl]
__global__ void k_split_w(const float* __restrict__ W, __nv_bfloat16* __restrict__ WP, int K) {
    int i = blockIdx.x * blockDim.x + threadIdx.x;
    if (i >= K * 32) return;
    int row = i >> 5, c4 = (i & 31) * 4;
    float4 v = ((const float4*)W)[i];
    uint2 h, l; split4(v, h, l);
    *(uint2*)(WP + (size_t)row * 128 + c4)       = h;
    *(uint2*)(WP + (size_t)(K + row) * 128 + c4) = l;
}

// ---------------- CSR build ----------------
__global__ void k_zero_counts() {
    int i = blockIdx.x * blockDim.x + threadIdx.x;
    if (i < NN) g_counts[i] = 0;
}

__global__ void k_hist(const int* __restrict__ dst) {
    int i = blockIdx.x * blockDim.x + threadIdx.x;
    if (i < EE / 4) {
        int4 d = ((const int4*)dst)[i];
        atomicAdd(&g_counts[d.x], 1);
        atomicAdd(&g_counts[d.y], 1);
        atomicAdd(&g_counts[d.z], 1);
        atomicAdd(&g_counts[d.w], 1);
    }
}

__global__ void k_scan_part() {
    __shared__ int sm[256];
    int i = blockIdx.x * 256 + threadIdx.x;
    sm[threadIdx.x] = (i < NN) ? g_counts[i] : 0;
    __syncthreads();
#pragma unroll
    for (int off = 128; off > 0; off >>= 1) {
        if (threadIdx.x < off) sm[threadIdx.x] += sm[threadIdx.x + off];
        __syncthreads();
    }
    if (threadIdx.x == 0) g_bsum[blockIdx.x] = sm[0];
}

__global__ void k_scan_top() {   // 1 block, 512 threads
    __shared__ int sm[512];
    int t = threadIdx.x;
    sm[t] = (t < NBLK) ? g_bsum[t] : 0;
    __syncthreads();
    for (int off = 1; off < 512; off <<= 1) {
        int v = (t >= off) ? sm[t - off] : 0;
        __syncthreads();
        sm[t] += v;
        __syncthreads();
    }
    if (t < NBLK) g_boff[t] = (t == 0) ? 0 : sm[t - 1];
}

__global__ void k_scan_write() {
    int b = blockIdx.x, t = threadIdx.x;
    int i = b * 256 + t;
    int c = (i < NN) ? g_counts[i] : 0;
    int lane = t & 31, w = t >> 5;
    int v = c;
#pragma unroll
    for (int off = 1; off < 32; off <<= 1) {
        int u = __shfl_up_sync(0xffffffffu, v, off);
        if (lane >= off) v += u;
    }
    __shared__ int wsum[8];
    if (lane == 31) wsum[w] = v;
    __syncthreads();
    if (w == 0) {
        int x = (lane < 8) ? wsum[lane] : 0;
#pragma unroll
        for (int off = 1; off < 8; off <<= 1) {
            int u = __shfl_up_sync(0xffffffffu, x, off);
            if (lane >= off) x += u;
        }
        if (lane < 8) wsum[lane] = x;
    }
    __syncthreads();
    int excl = v - c + ((w > 0) ? wsum[w - 1] : 0) + g_boff[b];
    if (i < NN) {
        g_row[i]    = excl;
        g_cursor[i] = excl;
        g_dinv[i]   = rsqrtf((float)(c + 1));
    }
    if (i == NN - 1) g_row[NN] = excl + c;
}

__global__ void k_scatter(const int* __restrict__ src, const int* __restrict__ dst) {
    int i = blockIdx.x * blockDim.x + threadIdx.x;
    if (i < EE / 4) {
        int4 s = ((const int4*)src)[i];
        int4 d = ((const int4*)dst)[i];
        int p;
        p = atomicAdd(&g_cursor[d.x], 1); g_csrc[p] = s.x;
        p = atomicAdd(&g_cursor[d.y], 1); g_csrc[p] = s.y;
        p = atomicAdd(&g_cursor[d.z], 1); g_csrc[p] = s.z;
        p = atomicAdd(&g_cursor[d.w], 1); g_csrc[p] = s.w;
    }
}

// ---------------- fused-split GEMM: C[.,128] = A_fp32[.,K] * W[K,128] ----------------
// A converted on the fly to (ah,al); W pre-split as WP=[Wh;Wl].
// C = ah*Wh + al*Wh + ah*Wl   (3-term split-bf16, fp32 accumulate)
template <int K>
__global__ __launch_bounds__(256) void fgemm128(
    const float* __restrict__ A, const __nv_bfloat16* __restrict__ WP,
    float* __restrict__ C, int M)
{
    constexpr int BM = 128, BK = 32;
    constexpr int LDA = BK + 8;    // 40
    constexpr int LDB = 128 + 8;   // 136
    constexpr int T = K / BK;

    extern __shared__ char smem[];
    float*          sAf = (float*)smem;                               // 2 * 128*32 f32 = 32KB
    __nv_bfloat16*  sAh = (__nv_bfloat16*)(smem + 2 * BM * BK * 4);   // 2 * 128*40
    __nv_bfloat16*  sAl = sAh + 2 * BM * LDA;                         // 2 * 128*40
    __nv_bfloat16*  sBh = sAl + 2 * BM * LDA;                         // 2 * 32*136
    __nv_bfloat16*  sBl = sBh + 2 * BK * LDB;                         // 2 * 32*136

    int tid  = threadIdx.x;
    int warp = tid >> 5;
    int wm   = warp >> 1;    // 0..3
    int wn   = warp & 1;     // 0..1
    size_t rowBase = (size_t)blockIdx.x * BM;

    auto issue = [&](int t) {
        int st = t & 1;
        int k0 = t * BK;
        // A: 128x32 fp32 = 1024 float4 chunks, 4 per thread
#pragma unroll
        for (int rep = 0; rep < 4; rep++) {
            int i = tid + rep * 256;
            int r = i >> 3, c4 = (i & 7) * 4;
            size_t gr = rowBase + r;
            float* dstp = &sAf[st * BM * BK + r * BK + c4];
            if (gr < (size_t)M)
                __pipeline_memcpy_async(dstp, &A[gr * K + k0 + c4], 16);
            else
                *(float4*)dstp = make_float4(0.f, 0.f, 0.f, 0.f);
        }
        // B: 32x128 bf16 per matrix = 512 16B chunks, 2 per thread each
#pragma unroll
        for (int rep = 0; rep < 2; rep++) {
            int i = tid + rep * 256;
            int r = i >> 4, c8 = (i & 15) * 8;
            __pipeline_memcpy_async(&sBh[st * BK * LDB + r * LDB + c8],
                                    &WP[(size_t)(k0 + r) * 128 + c8], 16);
            __pipeline_memcpy_async(&sBl[st * BK * LDB + r * LDB + c8],
                                    &WP[(size_t)(K + k0 + r) * 128 + c8], 16);
        }
    };

    wmma::fragment<wmma::accumulator, 16, 16, 16, float> acc[2][4];
#pragma unroll
    for (int i = 0; i < 2; i++)
#pragma unroll
        for (int j = 0; j < 4; j++) wmma::fill_fragment(acc[i][j], 0.f);

    issue(0);
    __pipeline_commit();

    for (int t = 0; t < T; t++) {
        int st = t & 1;
        __pipeline_wait_prior(0);
        __syncthreads();          // stage-t data visible; all prior MMA complete

        // convert fp32 stage -> hi/lo bf16 tiles
#pragma unroll
        for (int rep = 0; rep < 4; rep++) {
            int i = tid + rep * 256;
            int r = i >> 3, c4 = (i & 7) * 4;
            float4 v = *(float4*)&sAf[st * BM * BK + r * BK + c4];
            uint2 h, l; split4(v, h, l);
            *(uint2*)&sAh[st * BM * LDA + r * LDA + c4] = h;
            *(uint2*)&sAl[st * BM * LDA + r * LDA + c4] = l;
        }
        if (t + 1 < T) { issue(t + 1); __pipeline_commit(); }
        __syncthreads();          // bf16 tiles visible

#pragma unroll
        for (int kk = 0; kk < BK; kk += 16) {
            wmma::fragment<wmma::matrix_a, 16, 16, 16, __nv_bfloat16, wmma::row_major> ah[2], al[2];
#pragma unroll
            for (int i = 0; i < 2; i++) {
                int r = wm * 32 + i * 16;
                wmma::load_matrix_sync(ah[i], &sAh[st * BM * LDA + r * LDA + kk], LDA);
                wmma::load_matrix_sync(al[i], &sAl[st * BM * LDA + r * LDA + kk], LDA);
            }
#pragma unroll
            for (int j = 0; j < 4; j++) {
                int c = wn * 64 + j * 16;
                wmma::fragment<wmma::matrix_b, 16, 16, 16, __nv_bfloat16, wmma::row_major> bh, bl;
                wmma::load_matrix_sync(bh, &sBh[st * BK * LDB + kk * LDB + c], LDB);
                wmma::load_matrix_sync(bl, &sBl[st * BK * LDB + kk * LDB + c], LDB);
#pragma unroll
                for (int i = 0; i < 2; i++) {
                    wmma::mma_sync(acc[i][j], ah[i], bh, acc[i][j]);
                    wmma::mma_sync(acc[i][j], al[i], bh, acc[i][j]);
                    wmma::mma_sync(acc[i][j], ah[i], bl, acc[i][j]);
                }
            }
        }
    }

#pragma unroll
    for (int i = 0; i < 2; i++)
#pragma unroll
        for (int j = 0; j < 4; j++) {
            size_t r = rowBase + wm * 32 + i * 16;
            int c = wn * 64 + j * 16;
            wmma::store_matrix_sync(&C[r * 128 + c], acc[i][j], 128, wmma::mem_row_major);
        }
}

constexpr int FGEMM_SMEM = 2 * 128 * 32 * 4            // sAf
                         + 2 * 2 * 128 * 40 * 2        // sAh + sAl
                         + 2 * 2 * 32 * 136 * 2;       // sBh + sBl

// ---------------- small GEMM: C[M,16] = A[M,128] * W[128,16] ----------------
__global__ __launch_bounds__(256) void gemm16(
    const float* __restrict__ A, const float* __restrict__ W,
    float* __restrict__ C, int M)
{
    __shared__ float xs[64][132];
    __shared__ float ws[128][16];

    int tid = threadIdx.x;
    int r0 = blockIdx.x * 64;

    for (int i = tid; i < 2048; i += 256) {
        int row = i >> 5;
        int c4 = i & 31;
        int gr = r0 + row;
        float4 v = (gr < M) ? *(const float4*)(A + (size_t)gr * 128 + c4 * 4)
                            : make_float4(0.f, 0.f, 0.f, 0.f);
        *(float4*)(&xs[row][c4 * 4]) = v;
    }
    for (int i = tid; i < 2048; i += 256) ws[i >> 4][i & 15] = W[i];
    __syncthreads();

    int col = tid & 15;
    int rq  = tid >> 4;
    float acc[4] = {0.f, 0.f, 0.f, 0.f};
    for (int k = 0; k < 128; k++) {
        float w = ws[k][col];
#pragma unroll
        for (int r = 0; r < 4; r++)
            acc[r] = fmaf(xs[rq * 4 + r][k], w, acc[r]);
    }
#pragma unroll
    for (int r = 0; r < 4; r++) {
        int gr = r0 + rq * 4 + r;
        if (gr < M) C[(size_t)gr * 16 + col] = acc[r];
    }
}

// ---------------- aggregation, F=128 ----------------
template <bool RELU>
__global__ __launch_bounds__(256) void agg128(
    const float4* __restrict__ h, const float* __restrict__ bias,
    float4* __restrict__ outF)
{
    int warp = (blockIdx.x * blockDim.x + threadIdx.x) >> 5;
    int lane = threadIdx.x & 31;
    if (warp >= NN) return;
    int v = warp;

    float dv = g_dinv[v];
    float4 self = h[(size_t)v * 32 + lane];
    float4 acc;
    acc.x = dv * self.x; acc.y = dv * self.y;
    acc.z = dv * self.z; acc.w = dv * self.w;

    int rs = g_row[v], re = g_row[v + 1];
    int base = rs;
    for (; base + 32 <= re; base += 32) {
        int   s = g_csrc[base + lane];
        float d = g_dinv[s];
#pragma unroll
        for (int j = 0; j < 32; j++) {
            int   sj = __shfl_sync(0xffffffffu, s, j);
            float dj = __shfl_sync(0xffffffffu, d, j);
            float4 hv = h[(size_t)sj * 32 + lane];
            acc.x = fmaf(dj, hv.x, acc.x);
            acc.y = fmaf(dj, hv.y, acc.y);
            acc.z = fmaf(dj, hv.z, acc.z);
            acc.w = fmaf(dj, hv.w, acc.w);
        }
    }
    if (base < re) {
        int cnt = re - base;
        int   s = (lane < cnt) ? g_csrc[base + lane] : 0;
        float d = (lane < cnt) ? g_dinv[s] : 0.f;
        for (int j = 0; j < cnt; j++) {
            int   sj = __shfl_sync(0xffffffffu, s, j);
            float dj = __shfl_sync(0xffffffffu, d, j);
            float4 hv = h[(size_t)sj * 32 + lane];
            acc.x = fmaf(dj, hv.x, acc.x);
            acc.y = fmaf(dj, hv.y, acc.y);
            acc.z = fmaf(dj, hv.z, acc.z);
            acc.w = fmaf(dj, hv.w, acc.w);
        }
    }

    float4 bb = *(const float4*)(bias + 4 * lane);
    acc.x = fmaf(acc.x, dv, bb.x);
    acc.y = fmaf(acc.y, dv, bb.y);
    acc.z = fmaf(acc.z, dv, bb.z);
    acc.w = fmaf(acc.w, dv, bb.w);
    if (RELU) {
        acc.x = fmaxf(acc.x, 0.f); acc.y = fmaxf(acc.y, 0.f);
        acc.z = fmaxf(acc.z, 0.f); acc.w = fmaxf(acc.w, 0.f);
    }
    outF[(size_t)v * 32 + lane] = acc;
}

// ---------------- aggregation, F=16 ----------------
__global__ __launch_bounds__(256) void agg16(
    const float* __restrict__ h, const float* __restrict__ bias,
    float* __restrict__ out)
{
    int warp = (blockIdx.x * blockDim.x + threadIdx.x) >> 5;
    int lane = threadIdx.x & 31;
    if (warp >= NN) return;
    int v = warp;

    float dv = g_dinv[v];
    float acc = (lane < 16) ? dv * h[(size_t)v * 16 + lane] : 0.f;

    int rs = g_row[v], re = g_row[v + 1];
    int base = rs;
    for (; base + 32 <= re; base += 32) {
        int   s = g_csrc[base + lane];
        float d = g_dinv[s];
#pragma unroll
        for (int j = 0; j < 32; j++) {
            int   sj = __shfl_sync(0xffffffffu, s, j);
            float dj = __shfl_sync(0xffffffffu, d, j);
            if (lane < 16) acc = fmaf(dj, h[(size_t)sj * 16 + lane], acc);
        }
    }
    if (base < re) {
        int cnt = re - base;
        int   s = (lane < cnt) ? g_csrc[base + lane] : 0;
        float d = (lane < cnt) ? g_dinv[s] : 0.f;
        for (int j = 0; j < cnt; j++) {
            int   sj = __shfl_sync(0xffffffffu, s, j);
            float dj = __shfl_sync(0xffffffffu, d, j);
            if (lane < 16) acc = fmaf(dj, h[(size_t)sj * 16 + lane], acc);
        }
    }

    if (lane < 16) {
        acc = fmaf(acc, dv, bias[lane]);
        out[(size_t)v * 16 + lane] = acc;
    }
}

// ---------------- launch ----------------
extern "C" void kernel_launch(void* const* d_in, const int* in_sizes, int n_in,
                              void* d_out, int out_size)
{
    const float* x  = (const float*)d_in[0];
    const int*   ei = (const int*)d_in[1];
    const float* W1 = (const float*)d_in[2];
    const float* b1 = (const float*)d_in[3];
    const float* W2 = (const float*)d_in[4];
    const float* b2 = (const float*)d_in[5];
    const float* W3 = (const float*)d_in[6];
    const float* b3 = (const float*)d_in[7];
    float* out = (float*)d_out;

    float *pH, *pHB, *pC16;
    __nv_bfloat16 *pW1P, *pW2P;
    cudaGetSymbolAddress((void**)&pH,   g_h);
    cudaGetSymbolAddress((void**)&pHB,  g_hb);
    cudaGetSymbolAddress((void**)&pC16, g_c16);
    cudaGetSymbolAddress((void**)&pW1P, g_w1p);
    cudaGetSymbolAddress((void**)&pW2P, g_w2p);

    static bool attrs_set = false;
    if (!attrs_set) {
        cudaFuncSetAttribute(fgemm128<256>, cudaFuncAttributeMaxDynamicSharedMemorySize, FGEMM_SMEM);
        cudaFuncSetAttribute(fgemm128<128>, cudaFuncAttributeMaxDynamicSharedMemorySize, FGEMM_SMEM);
        attrs_set = true;
    }

    const int* e_src = ei;
    const int* e_dst = ei + EE;

    const int AGG_BLOCKS  = (NN + 7) / 8;
    const int GEMM_BLOCKS = MPAD / 128;  // 782

    // 1-3: W1 split, zero, hist
    k_split_w<<<(256 * 32 + 255) / 256, 256>>>(W1, pW1P, 256);
    k_zero_counts<<<(NN + 255) / 256, 256>>>();
    k_hist<<<(EE / 4 + 255) / 256, 256>>>(e_dst);

    // 4: layer-1 GEMM (profiled slot)
    fgemm128<256><<<GEMM_BLOCKS, 256, FGEMM_SMEM>>>(x, pW1P, pH, NN);

    // 5-9: scan (3-phase), scatter, W2 split
    k_scan_part<<<NBLK, 256>>>();
    k_scan_top<<<1, 512>>>();
    k_scan_write<<<NBLK, 256>>>();
    k_scatter<<<(EE / 4 + 255) / 256, 256>>>(e_src, e_dst);
    k_split_w<<<(128 * 32 + 255) / 256, 256>>>(W2, pW2P, 128);

    // Layer 1 aggregation
    agg128<true><<<AGG_BLOCKS, 256>>>((const float4*)pH, b1, (float4*)pHB);

    // Layer 2
    fgemm128<128><<<GEMM_BLOCKS, 256, FGEMM_SMEM>>>(pHB, pW2P, pH, NN);
    agg128<true><<<AGG_BLOCKS, 256>>>((const float4*)pH, b2, (float4*)pHB);

    // Layer 3
    gemm16<<<(NN + 63) / 64, 256>>>(pHB, W3, pC16, NN);
    agg16<<<AGG_BLOCKS, 256>>>(pC16, b3, out);
}

// round 5
// speedup vs baseline: 1.6471x; 1.0329x over previous
#include <cuda_runtime.h>
#include <cuda_bf16.h>
#include <cuda_pipeline.h>
#include <mma.h>
#include <cstdint>

using namespace nvcuda;

#define NN 100000
#define EE 1600000
#define MPAD 100096   // 782 * 128
#define NBLK 391      // ceil(NN/256)

// ---------------- scratch ----------------
__device__ int   g_counts[NN];
__device__ int   g_bsum[NBLK];
__device__ int   g_boff[NBLK];
__device__ int   g_row[NN + 1];
__device__ int   g_cursor[NN];
__device__ float g_dinv[NN];
__device__ int   g_csrc[EE];

__device__ float          g_h[(size_t)MPAD * 128];   // GEMM out (agg input)
__device__ float          g_hb[(size_t)MPAD * 128];  // agg out (next GEMM input)
__device__ float          g_c16[(size_t)MPAD * 16];
__device__ __nv_bfloat16  g_w1p[512 * 128];          // [W1h ; W1l]
__device__ __nv_bfloat16  g_w2p[256 * 128];          // [W2h ; W2l]

// ---------------- helpers ----------------
__device__ __forceinline__ void split4(float4 v, uint2& hi, uint2& lo) {
    __align__(8) __nv_bfloat16 h[4], l[4];
    float f[4] = {v.x, v.y, v.z, v.w};
#pragma unroll
    for (int i = 0; i < 4; i++) {
        h[i] = __float2bfloat16_rn(f[i]);
        l[i] = __float2bfloat16_rn(f[i] - __bfloat162float(h[i]));
    }
    hi = *(uint2*)h;
    lo = *(uint2*)l;
}

// W[K,128] -> WP[2K,128] = [Wh ; Wl]
__global__ void k_split_w(const float* __restrict__ W, __nv_bfloat16* __restrict__ WP, int K) {
    int i = blockIdx.x * blockDim.x + threadIdx.x;
    if (i >= K * 32) return;
    int row = i >> 5, c4 = (i & 31) * 4;
    float4 v = ((const float4*)W)[i];
    uint2 h, l; split4(v, h, l);
    *(uint2*)(WP + (size_t)row * 128 + c4)       = h;
    *(uint2*)(WP + (size_t)(K + row) * 128 + c4) = l;
}

// ---------------- CSR build ----------------
__global__ void k_zero_counts() {
    int i = blockIdx.x * blockDim.x + threadIdx.x;
    if (i < NN) g_counts[i] = 0;
}

__global__ void k_hist(const int* __restrict__ dst) {
    int i = blockIdx.x * blockDim.x + threadIdx.x;
    if (i < EE / 4) {
        int4 d = ((const int4*)dst)[i];
        atomicAdd(&g_counts[d.x], 1);
        atomicAdd(&g_counts[d.y], 1);
        atomicAdd(&g_counts[d.z], 1);
        atomicAdd(&g_counts[d.w], 1);
    }
}

__global__ void k_scan_part() {
    __shared__ int sm[256];
    int i = blockIdx.x * 256 + threadIdx.x;
    sm[threadIdx.x] = (i < NN) ? g_counts[i] : 0;
    __syncthreads();
#pragma unroll
    for (int off = 128; off > 0; off >>= 1) {
        if (threadIdx.x < off) sm[threadIdx.x] += sm[threadIdx.x + off];
        __syncthreads();
    }
    if (threadIdx.x == 0) g_bsum[blockIdx.x] = sm[0];
}

__global__ void k_scan_top() {   // 1 block, 512 threads
    __shared__ int sm[512];
    int t = threadIdx.x;
    sm[t] = (t < NBLK) ? g_bsum[t] : 0;
    __syncthreads();
    for (int off = 1; off < 512; off <<= 1) {
        int v = (t >= off) ? sm[t - off] : 0;
        __syncthreads();
        sm[t] += v;
        __syncthreads();
    }
    if (t < NBLK) g_boff[t] = (t == 0) ? 0 : sm[t - 1];
}

__global__ void k_scan_write() {
    int b = blockIdx.x, t = threadIdx.x;
    int i = b * 256 + t;
    int c = (i < NN) ? g_counts[i] : 0;
    int lane = t & 31, w = t >> 5;
    int v = c;
#pragma unroll
    for (int off = 1; off < 32; off <<= 1) {
        int u = __shfl_up_sync(0xffffffffu, v, off);
        if (lane >= off) v += u;
    }
    __shared__ int wsum[8];
    if (lane == 31) wsum[w] = v;
    __syncthreads();
    if (w == 0) {
        int x = (lane < 8) ? wsum[lane] : 0;
#pragma unroll
        for (int off = 1; off < 8; off <<= 1) {
            int u = __shfl_up_sync(0xffffffffu, x, off);
            if (lane >= off) x += u;
        }
        if (lane < 8) wsum[lane] = x;
    }
    __syncthreads();
    int excl = v - c + ((w > 0) ? wsum[w - 1] : 0) + g_boff[b];
    if (i < NN) {
        g_row[i]    = excl;
        g_cursor[i] = excl;
        g_dinv[i]   = rsqrtf((float)(c + 1));
    }
    if (i == NN - 1) g_row[NN] = excl + c;
}

__global__ void k_scatter(const int* __restrict__ src, const int* __restrict__ dst) {
    int i = blockIdx.x * blockDim.x + threadIdx.x;
    if (i < EE / 4) {
        int4 s = ((const int4*)src)[i];
        int4 d = ((const int4*)dst)[i];
        int p;
        p = atomicAdd(&g_cursor[d.x], 1); g_csrc[p] = s.x;
        p = atomicAdd(&g_cursor[d.y], 1); g_csrc[p] = s.y;
        p = atomicAdd(&g_cursor[d.z], 1); g_csrc[p] = s.z;
        p = atomicAdd(&g_cursor[d.w], 1); g_csrc[p] = s.w;
    }
}

// ---------------- fused-split GEMM: C[.,128] = A_fp32[.,K] * W[K,128] ----------------
// A staged through registers, converted to (ah,al) bf16 in-regs, STS to smem.
// W pre-split as WP=[Wh;Wl]. C = ah*Wh + al*Wh + ah*Wl, fp32 accumulate.
template <int K>
__global__ __launch_bounds__(256, 2) void fgemm128(
    const float* __restrict__ A, const __nv_bfloat16* __restrict__ WP,
    float* __restrict__ C, int M)
{
    constexpr int BM = 128, BK = 32;
    constexpr int LDA = BK + 8;    // 40
    constexpr int LDB = 128 + 8;   // 136
    constexpr int T = K / BK;

    extern __shared__ char smem[];
    __nv_bfloat16* sAh = (__nv_bfloat16*)smem;                  // 2 * 128*40
    __nv_bfloat16* sAl = sAh + 2 * BM * LDA;                    // 2 * 128*40
    __nv_bfloat16* sBh = sAl + 2 * BM * LDA;                    // 2 * 32*136
    __nv_bfloat16* sBl = sBh + 2 * BK * LDB;                    // 2 * 32*136

    int tid  = threadIdx.x;
    int warp = tid >> 5;
    int wm   = warp >> 1;    // 0..3
    int wn   = warp & 1;     // 0..1
    size_t rowBase = (size_t)blockIdx.x * BM;

    // A per-thread: 4 float4 chunks; chunk i: r = i>>3, c4 = (i&7)*4
    float4 curA[4], nxtA[4];

    auto ldgA = [&](float4* buf, int t) {
        int k0 = t * BK;
#pragma unroll
        for (int rep = 0; rep < 4; rep++) {
            int i = tid + rep * 256;
            int r = i >> 3, c4 = (i & 7) * 4;
            size_t gr = rowBase + r;
            buf[rep] = (gr < (size_t)M) ? *(const float4*)&A[gr * K + k0 + c4]
                                        : make_float4(0.f, 0.f, 0.f, 0.f);
        }
    };
    auto stsA = [&](const float4* buf, int st) {
#pragma unroll
        for (int rep = 0; rep < 4; rep++) {
            int i = tid + rep * 256;
            int r = i >> 3, c4 = (i & 7) * 4;
            uint2 h, l; split4(buf[rep], h, l);
            *(uint2*)&sAh[st * BM * LDA + r * LDA + c4] = h;
            *(uint2*)&sAl[st * BM * LDA + r * LDA + c4] = l;
        }
    };
    auto issueB = [&](int t) {
        int st = t & 1, k0 = t * BK;
#pragma unroll
        for (int rep = 0; rep < 2; rep++) {
            int i = tid + rep * 256;
            int r = i >> 4, c8 = (i & 15) * 8;
            __pipeline_memcpy_async(&sBh[st * BK * LDB + r * LDB + c8],
                                    &WP[(size_t)(k0 + r) * 128 + c8], 16);
            __pipeline_memcpy_async(&sBl[st * BK * LDB + r * LDB + c8],
                                    &WP[(size_t)(K + k0 + r) * 128 + c8], 16);
        }
    };

    wmma::fragment<wmma::accumulator, 16, 16, 16, float> acc[2][4];
#pragma unroll
    for (int i = 0; i < 2; i++)
#pragma unroll
        for (int j = 0; j < 4; j++) wmma::fill_fragment(acc[i][j], 0.f);

    ldgA(curA, 0);
    issueB(0);
    __pipeline_commit();

    for (int t = 0; t < T; t++) {
        int st = t & 1;

        stsA(curA, st);                 // convert regs -> bf16 smem tiles
        __pipeline_wait_prior(0);       // B stage t complete (this thread's copies)
        __syncthreads();                // all STS + all cp.async visible

        if (t + 1 < T) ldgA(nxtA, t + 1);   // overlap LDG latency with MMA below

#pragma unroll
        for (int kk = 0; kk < BK; kk += 16) {
            wmma::fragment<wmma::matrix_a, 16, 16, 16, __nv_bfloat16, wmma::row_major> ah[2], al[2];
#pragma unroll
            for (int i = 0; i < 2; i++) {
                int r = wm * 32 + i * 16;
                wmma::load_matrix_sync(ah[i], &sAh[st * BM * LDA + r * LDA + kk], LDA);
                wmma::load_matrix_sync(al[i], &sAl[st * BM * LDA + r * LDA + kk], LDA);
            }
#pragma unroll
            for (int j = 0; j < 4; j++) {
                int c = wn * 64 + j * 16;
                wmma::fragment<wmma::matrix_b, 16, 16, 16, __nv_bfloat16, wmma::row_major> bh, bl;
                wmma::load_matrix_sync(bh, &sBh[st * BK * LDB + kk * LDB + c], LDB);
                wmma::load_matrix_sync(bl, &sBl[st * BK * LDB + kk * LDB + c], LDB);
#pragma unroll
                for (int i = 0; i < 2; i++) {
                    wmma::mma_sync(acc[i][j], ah[i], bh, acc[i][j]);
                    wmma::mma_sync(acc[i][j], al[i], bh, acc[i][j]);
                    wmma::mma_sync(acc[i][j], ah[i], bl, acc[i][j]);
                }
            }
        }
        __syncthreads();                // all MMA reads of stage st done

        if (t + 1 < T) {
            issueB(t + 1);              // safe: everyone is past MMA(t)
            __pipeline_commit();
#pragma unroll
            for (int rep = 0; rep < 4; rep++) curA[rep] = nxtA[rep];
        }
    }

#pragma unroll
    for (int i = 0; i < 2; i++)
#pragma unroll
        for (int j = 0; j < 4; j++) {
            size_t r = rowBase + wm * 32 + i * 16;
            int c = wn * 64 + j * 16;
            wmma::store_matrix_sync(&C[r * 128 + c], acc[i][j], 128, wmma::mem_row_major);
        }
}

constexpr int FGEMM_SMEM = 2 * 2 * 128 * 40 * 2        // sAh + sAl
                         + 2 * 2 * 32 * 136 * 2;       // sBh + sBl  = 75776

// ---------------- small GEMM: C[M,16] = A[M,128] * W[128,16] ----------------
__global__ __launch_bounds__(256) void gemm16(
    const float* __restrict__ A, const float* __restrict__ W,
    float* __restrict__ C, int M)
{
    __shared__ float xs[64][132];
    __shared__ float ws[128][16];

    int tid = threadIdx.x;
    int r0 = blockIdx.x * 64;

    for (int i = tid; i < 2048; i += 256) {
        int row = i >> 5;
        int c4 = i & 31;
        int gr = r0 + row;
        float4 v = (gr < M) ? *(const float4*)(A + (size_t)gr * 128 + c4 * 4)
                            : make_float4(0.f, 0.f, 0.f, 0.f);
        *(float4*)(&xs[row][c4 * 4]) = v;
    }
    for (int i = tid; i < 2048; i += 256) ws[i >> 4][i & 15] = W[i];
    __syncthreads();

    int col = tid & 15;
    int rq  = tid >> 4;
    float acc[4] = {0.f, 0.f, 0.f, 0.f};
    for (int k = 0; k < 128; k++) {
        float w = ws[k][col];
#pragma unroll
        for (int r = 0; r < 4; r++)
            acc[r] = fmaf(xs[rq * 4 + r][k], w, acc[r]);
    }
#pragma unroll
    for (int r = 0; r < 4; r++) {
        int gr = r0 + rq * 4 + r;
        if (gr < M) C[(size_t)gr * 16 + col] = acc[r];
    }
}

// ---------------- aggregation, F=128 ----------------
template <bool RELU>
__global__ __launch_bounds__(256) void agg128(
    const float4* __restrict__ h, const float* __restrict__ bias,
    float4* __restrict__ outF)
{
    int warp = (blockIdx.x * blockDim.x + threadIdx.x) >> 5;
    int lane = threadIdx.x & 31;
    if (warp >= NN) return;
    int v = warp;

    float dv = g_dinv[v];
    float4 self = h[(size_t)v * 32 + lane];
    float4 acc;
    acc.x = dv * self.x; acc.y = dv * self.y;
    acc.z = dv * self.z; acc.w = dv * self.w;

    int rs = g_row[v], re = g_row[v + 1];
    int base = rs;
    for (; base + 32 <= re; base += 32) {
        int   s = g_csrc[base + lane];
        float d = g_dinv[s];
#pragma unroll
        for (int j = 0; j < 32; j++) {
            int   sj = __shfl_sync(0xffffffffu, s, j);
            float dj = __shfl_sync(0xffffffffu, d, j);
            float4 hv = h[(size_t)sj * 32 + lane];
            acc.x = fmaf(dj, hv.x, acc.x);
            acc.y = fmaf(dj, hv.y, acc.y);
            acc.z = fmaf(dj, hv.z, acc.z);
            acc.w = fmaf(dj, hv.w, acc.w);
        }
    }
    if (base < re) {
        int cnt = re - base;
        int   s = (lane < cnt) ? g_csrc[base + lane] : 0;
        float d = (lane < cnt) ? g_dinv[s] : 0.f;
        for (int j = 0; j < cnt; j++) {
            int   sj = __shfl_sync(0xffffffffu, s, j);
            float dj = __shfl_sync(0xffffffffu, d, j);
            float4 hv = h[(size_t)sj * 32 + lane];
            acc.x = fmaf(dj, hv.x, acc.x);
            acc.y = fmaf(dj, hv.y, acc.y);
            acc.z = fmaf(dj, hv.z, acc.z);
            acc.w = fmaf(dj, hv.w, acc.w);
        }
    }

    float4 bb = *(const float4*)(bias + 4 * lane);
    acc.x = fmaf(acc.x, dv, bb.x);
    acc.y = fmaf(acc.y, dv, bb.y);
    acc.z = fmaf(acc.z, dv, bb.z);
    acc.w = fmaf(acc.w, dv, bb.w);
    if (RELU) {
        acc.x = fmaxf(acc.x, 0.f); acc.y = fmaxf(acc.y, 0.f);
        acc.z = fmaxf(acc.z, 0.f); acc.w = fmaxf(acc.w, 0.f);
    }
    outF[(size_t)v * 32 + lane] = acc;
}

// ---------------- aggregation, F=16 ----------------
__global__ __launch_bounds__(256) void agg16(
    const float* __restrict__ h, const float* __restrict__ bias,
    float* __restrict__ out)
{
    int warp = (blockIdx.x * blockDim.x + threadIdx.x) >> 5;
    int lane = threadIdx.x & 31;
    if (warp >= NN) return;
    int v = warp;

    float dv = g_dinv[v];
    float acc = (lane < 16) ? dv * h[(size_t)v * 16 + lane] : 0.f;

    int rs = g_row[v], re = g_row[v + 1];
    int base = rs;
    for (; base + 32 <= re; base += 32) {
        int   s = g_csrc[base + lane];
        float d = g_dinv[s];
#pragma unroll
        for (int j = 0; j < 32; j++) {
            int   sj = __shfl_sync(0xffffffffu, s, j);
            float dj = __shfl_sync(0xffffffffu, d, j);
            if (lane < 16) acc = fmaf(dj, h[(size_t)sj * 16 + lane], acc);
        }
    }
    if (base < re) {
        int cnt = re - base;
        int   s = (lane < cnt) ? g_csrc[base + lane] : 0;
        float d = (lane < cnt) ? g_dinv[s] : 0.f;
        for (int j = 0; j < cnt; j++) {
            int   sj = __shfl_sync(0xffffffffu, s, j);
            float dj = __shfl_sync(0xffffffffu, d, j);
            if (lane < 16) acc = fmaf(dj, h[(size_t)sj * 16 + lane], acc);
        }
    }

    if (lane < 16) {
        acc = fmaf(acc, dv, bias[lane]);
        out[(size_t)v * 16 + lane] = acc;
    }
}

// ---------------- launch ----------------
extern "C" void kernel_launch(void* const* d_in, const int* in_sizes, int n_in,
                              void* d_out, int out_size)
{
    const float* x  = (const float*)d_in[0];
    const int*   ei = (const int*)d_in[1];
    const float* W1 = (const float*)d_in[2];
    const float* b1 = (const float*)d_in[3];
    const float* W2 = (const float*)d_in[4];
    const float* b2 = (const float*)d_in[5];
    const float* W3 = (const float*)d_in[6];
    const float* b3 = (const float*)d_in[7];
    float* out = (float*)d_out;

    float *pH, *pHB, *pC16;
    __nv_bfloat16 *pW1P, *pW2P;
    cudaGetSymbolAddress((void**)&pH,   g_h);
    cudaGetSymbolAddress((void**)&pHB,  g_hb);
    cudaGetSymbolAddress((void**)&pC16, g_c16);
    cudaGetSymbolAddress((void**)&pW1P, g_w1p);
    cudaGetSymbolAddress((void**)&pW2P, g_w2p);

    static bool attrs_set = false;
    if (!attrs_set) {
        cudaFuncSetAttribute(fgemm128<256>, cudaFuncAttributeMaxDynamicSharedMemorySize, FGEMM_SMEM);
        cudaFuncSetAttribute(fgemm128<128>, cudaFuncAttributeMaxDynamicSharedMemorySize, FGEMM_SMEM);
        attrs_set = true;
    }

    const int* e_src = ei;
    const int* e_dst = ei + EE;

    const int AGG_BLOCKS  = (NN + 7) / 8;
    const int GEMM_BLOCKS = MPAD / 128;  // 782

    // 1-3: W1 split, zero, hist
    k_split_w<<<(256 * 32 + 255) / 256, 256>>>(W1, pW1P, 256);
    k_zero_counts<<<(NN + 255) / 256, 256>>>();
    k_hist<<<(EE / 4 + 255) / 256, 256>>>(e_dst);

    // 4: layer-1 GEMM (profiled slot)
    fgemm128<256><<<GEMM_BLOCKS, 256, FGEMM_SMEM>>>(x, pW1P, pH, NN);

    // 5-9: scan (3-phase), scatter, W2 split
    k_scan_part<<<NBLK, 256>>>();
    k_scan_top<<<1, 512>>>();
    k_scan_write<<<NBLK, 256>>>();
    k_scatter<<<(EE / 4 + 255) / 256, 256>>>(e_src, e_dst);
    k_split_w<<<(128 * 32 + 255) / 256, 256>>>(W2, pW2P, 128);

    // Layer 1 aggregation
    agg128<true><<<AGG_BLOCKS, 256>>>((const float4*)pH, b1, (float4*)pHB);

    // Layer 2
    fgemm128<128><<<GEMM_BLOCKS, 256, FGEMM_SMEM>>>(pHB, pW2P, pH, NN);
    agg128<true><<<AGG_BLOCKS, 256>>>((const float4*)pH, b2, (float4*)pHB);

    // Layer 3
    gemm16<<<(NN + 63) / 64, 256>>>(pHB, W3, pC16, NN);
    agg16<<<AGG_BLOCKS, 256>>>(pC16, b3, out);
}

// round 6
// speedup vs baseline: 1.8029x; 1.0945x over previous
#include <cuda_runtime.h>
#include <cuda_bf16.h>
#include <cuda_pipeline.h>
#include <mma.h>
#include <cstdint>

using namespace nvcuda;

#define NN 100000
#define EE 1600000
#define MPAD 100096   // 782 * 128
#define NBLK 391      // ceil(NN/256)

// ---------------- scratch ----------------
__device__ int   g_counts[NN];
__device__ int   g_bsum[NBLK];
__device__ int   g_boff[NBLK];
__device__ int   g_row[NN + 1];
__device__ int   g_cursor[NN];
__device__ float g_dinv[NN];
__device__ int   g_csrc[EE];

__device__ float          g_h[(size_t)MPAD * 128];   // GEMM out (agg input)
__device__ float          g_hb[(size_t)MPAD * 128];  // agg out (next GEMM input)
__device__ float          g_c16[(size_t)MPAD * 16];
__device__ __nv_bfloat16  g_w1p[512 * 128];          // [W1h ; W1l]
__device__ __nv_bfloat16  g_w2p[256 * 128];          // [W2h ; W2l]

// ---------------- helpers ----------------
__device__ __forceinline__ void split4(float4 v, uint2& hi, uint2& lo) {
    __align__(8) __nv_bfloat16 h[4], l[4];
    float f[4] = {v.x, v.y, v.z, v.w};
#pragma unroll
    for (int i = 0; i < 4; i++) {
        h[i] = __float2bfloat16_rn(f[i]);
        l[i] = __float2bfloat16_rn(f[i] - __bfloat162float(h[i]));
    }
    hi = *(uint2*)h;
    lo = *(uint2*)l;
}

// W[K,128] -> WP[2K,128] = [Wh ; Wl]
__global__ void k_split_w(const float* __restrict__ W, __nv_bfloat16* __restrict__ WP, int K) {
    int i = blockIdx.x * blockDim.x + threadIdx.x;
    if (i >= K * 32) return;
    int row = i >> 5, c4 = (i & 31) * 4;
    float4 v = ((const float4*)W)[i];
    uint2 h, l; split4(v, h, l);
    *(uint2*)(WP + (size_t)row * 128 + c4)       = h;
    *(uint2*)(WP + (size_t)(K + row) * 128 + c4) = l;
}

// ---------------- CSR build ----------------
__global__ void k_zero_counts() {
    int i = blockIdx.x * blockDim.x + threadIdx.x;
    if (i < NN) g_counts[i] = 0;
}

__global__ void k_hist(const int* __restrict__ dst) {
    int i = blockIdx.x * blockDim.x + threadIdx.x;
    if (i < EE / 4) {
        int4 d = ((const int4*)dst)[i];
        atomicAdd(&g_counts[d.x], 1);
        atomicAdd(&g_counts[d.y], 1);
        atomicAdd(&g_counts[d.z], 1);
        atomicAdd(&g_counts[d.w], 1);
    }
}

__global__ void k_scan_part() {
    __shared__ int sm[256];
    int i = blockIdx.x * 256 + threadIdx.x;
    sm[threadIdx.x] = (i < NN) ? g_counts[i] : 0;
    __syncthreads();
#pragma unroll
    for (int off = 128; off > 0; off >>= 1) {
        if (threadIdx.x < off) sm[threadIdx.x] += sm[threadIdx.x + off];
        __syncthreads();
    }
    if (threadIdx.x == 0) g_bsum[blockIdx.x] = sm[0];
}

__global__ void k_scan_top() {   // 1 block, 512 threads
    __shared__ int sm[512];
    int t = threadIdx.x;
    sm[t] = (t < NBLK) ? g_bsum[t] : 0;
    __syncthreads();
    for (int off = 1; off < 512; off <<= 1) {
        int v = (t >= off) ? sm[t - off] : 0;
        __syncthreads();
        sm[t] += v;
        __syncthreads();
    }
    if (t < NBLK) g_boff[t] = (t == 0) ? 0 : sm[t - 1];
}

__global__ void k_scan_write() {
    int b = blockIdx.x, t = threadIdx.x;
    int i = b * 256 + t;
    int c = (i < NN) ? g_counts[i] : 0;
    int lane = t & 31, w = t >> 5;
    int v = c;
#pragma unroll
    for (int off = 1; off < 32; off <<= 1) {
        int u = __shfl_up_sync(0xffffffffu, v, off);
        if (lane >= off) v += u;
    }
    __shared__ int wsum[8];
    if (lane == 31) wsum[w] = v;
    __syncthreads();
    if (w == 0) {
        int x = (lane < 8) ? wsum[lane] : 0;
#pragma unroll
        for (int off = 1; off < 8; off <<= 1) {
            int u = __shfl_up_sync(0xffffffffu, x, off);
            if (lane >= off) x += u;
        }
        if (lane < 8) wsum[lane] = x;
    }
    __syncthreads();
    int excl = v - c + ((w > 0) ? wsum[w - 1] : 0) + g_boff[b];
    if (i < NN) {
        g_row[i]    = excl;
        g_cursor[i] = excl;
        g_dinv[i]   = rsqrtf((float)(c + 1));
    }
    if (i == NN - 1) g_row[NN] = excl + c;
}

__global__ void k_scatter(const int* __restrict__ src, const int* __restrict__ dst) {
    int i = blockIdx.x * blockDim.x + threadIdx.x;
    if (i < EE / 4) {
        int4 s = ((const int4*)src)[i];
        int4 d = ((const int4*)dst)[i];
        int p;
        p = atomicAdd(&g_cursor[d.x], 1); g_csrc[p] = s.x;
        p = atomicAdd(&g_cursor[d.y], 1); g_csrc[p] = s.y;
        p = atomicAdd(&g_cursor[d.z], 1); g_csrc[p] = s.z;
        p = atomicAdd(&g_cursor[d.w], 1); g_csrc[p] = s.w;
    }
}

// ---------------- fused-split GEMM: C[.,128] = A_fp32[.,K] * W[K,128] ----------------
// Single __syncthreads per BK tile. A staged through registers (split to bf16 hi/lo),
// W pre-split as WP=[Wh;Wl]. C = ah*Wh + al*Wh + ah*Wl, fp32 accumulate.
template <int K>
__global__ __launch_bounds__(256, 2) void fgemm128(
    const float* __restrict__ A, const __nv_bfloat16* __restrict__ WP,
    float* __restrict__ C, int M)
{
    constexpr int BM = 128, BK = 32;
    constexpr int LDA = BK + 8;    // 40
    constexpr int LDB = 128 + 8;   // 136
    constexpr int T = K / BK;

    extern __shared__ char smem[];
    __nv_bfloat16* sAh = (__nv_bfloat16*)smem;                  // 2 * 128*40
    __nv_bfloat16* sAl = sAh + 2 * BM * LDA;
    __nv_bfloat16* sBh = sAl + 2 * BM * LDA;                    // 2 * 32*136
    __nv_bfloat16* sBl = sBh + 2 * BK * LDB;

    int tid  = threadIdx.x;
    int warp = tid >> 5;
    int wm   = warp >> 1;    // 0..3
    int wn   = warp & 1;     // 0..1
    size_t rowBase = (size_t)blockIdx.x * BM;

    float4 curA[4], nxtA[4];

    auto ldgA = [&](float4* buf, int t) {
        int k0 = t * BK;
#pragma unroll
        for (int rep = 0; rep < 4; rep++) {
            int i = tid + rep * 256;
            int r = i >> 3, c4 = (i & 7) * 4;
            size_t gr = rowBase + r;
            buf[rep] = (gr < (size_t)M) ? *(const float4*)&A[gr * K + k0 + c4]
                                        : make_float4(0.f, 0.f, 0.f, 0.f);
        }
    };
    auto stsA = [&](const float4* buf, int st) {
#pragma unroll
        for (int rep = 0; rep < 4; rep++) {
            int i = tid + rep * 256;
            int r = i >> 3, c4 = (i & 7) * 4;
            uint2 h, l; split4(buf[rep], h, l);
            *(uint2*)&sAh[st * BM * LDA + r * LDA + c4] = h;
            *(uint2*)&sAl[st * BM * LDA + r * LDA + c4] = l;
        }
    };
    auto issueB = [&](int t) {
        int st = t & 1, k0 = t * BK;
#pragma unroll
        for (int rep = 0; rep < 2; rep++) {
            int i = tid + rep * 256;
            int r = i >> 4, c8 = (i & 15) * 8;
            __pipeline_memcpy_async(&sBh[st * BK * LDB + r * LDB + c8],
                                    &WP[(size_t)(k0 + r) * 128 + c8], 16);
            __pipeline_memcpy_async(&sBl[st * BK * LDB + r * LDB + c8],
                                    &WP[(size_t)(K + k0 + r) * 128 + c8], 16);
        }
    };

    wmma::fragment<wmma::accumulator, 16, 16, 16, float> acc[2][4];
#pragma unroll
    for (int i = 0; i < 2; i++)
#pragma unroll
        for (int j = 0; j < 4; j++) wmma::fill_fragment(acc[i][j], 0.f);

    ldgA(curA, 0);
    issueB(0);
    __pipeline_commit();

    for (int t = 0; t < T; t++) {
        int st = t & 1;

        stsA(curA, st);              // stage st A tiles: last read by MMA(t-2), done at sync(t-1)
        __pipeline_wait_prior(0);    // B stage st arrived
        __syncthreads();             // all STS visible; all warps past MMA(t-1)

        if (t + 1 < T) {
            ldgA(nxtA, t + 1);       // LDG latency hides under MMA below
            issueB(t + 1);           // writes stage st^1: last read by MMA(t-1), done at sync above
            __pipeline_commit();
        }

#pragma unroll
        for (int kk = 0; kk < BK; kk += 16) {
            wmma::fragment<wmma::matrix_a, 16, 16, 16, __nv_bfloat16, wmma::row_major> ah[2], al[2];
#pragma unroll
            for (int i = 0; i < 2; i++) {
                int r = wm * 32 + i * 16;
                wmma::load_matrix_sync(ah[i], &sAh[st * BM * LDA + r * LDA + kk], LDA);
                wmma::load_matrix_sync(al[i], &sAl[st * BM * LDA + r * LDA + kk], LDA);
            }
#pragma unroll
            for (int j = 0; j < 4; j++) {
                int c = wn * 64 + j * 16;
                wmma::fragment<wmma::matrix_b, 16, 16, 16, __nv_bfloat16, wmma::row_major> bh, bl;
                wmma::load_matrix_sync(bh, &sBh[st * BK * LDB + kk * LDB + c], LDB);
                wmma::load_matrix_sync(bl, &sBl[st * BK * LDB + kk * LDB + c], LDB);
#pragma unroll
                for (int i = 0; i < 2; i++) {
                    wmma::mma_sync(acc[i][j], ah[i], bh, acc[i][j]);
                    wmma::mma_sync(acc[i][j], al[i], bh, acc[i][j]);
                    wmma::mma_sync(acc[i][j], ah[i], bl, acc[i][j]);
                }
            }
        }

#pragma unroll
        for (int rep = 0; rep < 4; rep++) curA[rep] = nxtA[rep];
    }

#pragma unroll
    for (int i = 0; i < 2; i++)
#pragma unroll
        for (int j = 0; j < 4; j++) {
            size_t r = rowBase + wm * 32 + i * 16;
            int c = wn * 64 + j * 16;
            wmma::store_matrix_sync(&C[r * 128 + c], acc[i][j], 128, wmma::mem_row_major);
        }
}

constexpr int FGEMM_SMEM = 2 * 2 * 128 * 40 * 2        // sAh + sAl
                         + 2 * 2 * 32 * 136 * 2;       // sBh + sBl  = 75776

// ---------------- small GEMM: C[M,16] = A[M,128] * W[128,16] ----------------
__global__ __launch_bounds__(256) void gemm16(
    const float* __restrict__ A, const float* __restrict__ W,
    float* __restrict__ C, int M)
{
    __shared__ float xs[64][132];
    __shared__ float ws[128][16];

    int tid = threadIdx.x;
    int r0 = blockIdx.x * 64;

    for (int i = tid; i < 2048; i += 256) {
        int row = i >> 5;
        int c4 = i & 31;
        int gr = r0 + row;
        float4 v = (gr < M) ? *(const float4*)(A + (size_t)gr * 128 + c4 * 4)
                            : make_float4(0.f, 0.f, 0.f, 0.f);
        *(float4*)(&xs[row][c4 * 4]) = v;
    }
    for (int i = tid; i < 2048; i += 256) ws[i >> 4][i & 15] = W[i];
    __syncthreads();

    int col = tid & 15;
    int rq  = tid >> 4;
    float acc[4] = {0.f, 0.f, 0.f, 0.f};
    for (int k = 0; k < 128; k++) {
        float w = ws[k][col];
#pragma unroll
        for (int r = 0; r < 4; r++)
            acc[r] = fmaf(xs[rq * 4 + r][k], w, acc[r]);
    }
#pragma unroll
    for (int r = 0; r < 4; r++) {
        int gr = r0 + rq * 4 + r;
        if (gr < M) C[(size_t)gr * 16 + col] = acc[r];
    }
}

// ---------------- aggregation, F=128 ----------------
template <bool RELU>
__global__ __launch_bounds__(256) void agg128(
    const float4* __restrict__ h, const float* __restrict__ bias,
    float4* __restrict__ outF)
{
    int warp = (blockIdx.x * blockDim.x + threadIdx.x) >> 5;
    int lane = threadIdx.x & 31;
    if (warp >= NN) return;
    int v = warp;

    float dv = g_dinv[v];
    float4 self = h[(size_t)v * 32 + lane];
    float4 acc;
    acc.x = dv * self.x; acc.y = dv * self.y;
    acc.z = dv * self.z; acc.w = dv * self.w;

    int rs = g_row[v], re = g_row[v + 1];
    int base = rs;
    for (; base + 32 <= re; base += 32) {
        int   s = g_csrc[base + lane];
        float d = g_dinv[s];
#pragma unroll
        for (int j = 0; j < 32; j++) {
            int   sj = __shfl_sync(0xffffffffu, s, j);
            float dj = __shfl_sync(0xffffffffu, d, j);
            float4 hv = h[(size_t)sj * 32 + lane];
            acc.x = fmaf(dj, hv.x, acc.x);
            acc.y = fmaf(dj, hv.y, acc.y);
            acc.z = fmaf(dj, hv.z, acc.z);
            acc.w = fmaf(dj, hv.w, acc.w);
        }
    }
    if (base < re) {
        int cnt = re - base;
        int   s = (lane < cnt) ? g_csrc[base + lane] : 0;
        float d = (lane < cnt) ? g_dinv[s] : 0.f;
        for (int j = 0; j < cnt; j++) {
            int   sj = __shfl_sync(0xffffffffu, s, j);
            float dj = __shfl_sync(0xffffffffu, d, j);
            float4 hv = h[(size_t)sj * 32 + lane];
            acc.x = fmaf(dj, hv.x, acc.x);
            acc.y = fmaf(dj, hv.y, acc.y);
            acc.z = fmaf(dj, hv.z, acc.z);
            acc.w = fmaf(dj, hv.w, acc.w);
        }
    }

    float4 bb = *(const float4*)(bias + 4 * lane);
    acc.x = fmaf(acc.x, dv, bb.x);
    acc.y = fmaf(acc.y, dv, bb.y);
    acc.z = fmaf(acc.z, dv, bb.z);
    acc.w = fmaf(acc.w, dv, bb.w);
    if (RELU) {
        acc.x = fmaxf(acc.x, 0.f); acc.y = fmaxf(acc.y, 0.f);
        acc.z = fmaxf(acc.z, 0.f); acc.w = fmaxf(acc.w, 0.f);
    }
    outF[(size_t)v * 32 + lane] = acc;
}

// ---------------- aggregation, F=16 ----------------
__global__ __launch_bounds__(256) void agg16(
    const float* __restrict__ h, const float* __restrict__ bias,
    float* __restrict__ out)
{
    int warp = (blockIdx.x * blockDim.x + threadIdx.x) >> 5;
    int lane = threadIdx.x & 31;
    if (warp >= NN) return;
    int v = warp;

    float dv = g_dinv[v];
    float acc = (lane < 16) ? dv * h[(size_t)v * 16 + lane] : 0.f;

    int rs = g_row[v], re = g_row[v + 1];
    int base = rs;
    for (; base + 32 <= re; base += 32) {
        int   s = g_csrc[base + lane];
        float d = g_dinv[s];
#pragma unroll
        for (int j = 0; j < 32; j++) {
            int   sj = __shfl_sync(0xffffffffu, s, j);
            float dj = __shfl_sync(0xffffffffu, d, j);
            if (lane < 16) acc = fmaf(dj, h[(size_t)sj * 16 + lane], acc);
        }
    }
    if (base < re) {
        int cnt = re - base;
        int   s = (lane < cnt) ? g_csrc[base + lane] : 0;
        float d = (lane < cnt) ? g_dinv[s] : 0.f;
        for (int j = 0; j < cnt; j++) {
            int   sj = __shfl_sync(0xffffffffu, s, j);
            float dj = __shfl_sync(0xffffffffu, d, j);
            if (lane < 16) acc = fmaf(dj, h[(size_t)sj * 16 + lane], acc);
        }
    }

    if (lane < 16) {
        acc = fmaf(acc, dv, bias[lane]);
        out[(size_t)v * 16 + lane] = acc;
    }
}

// ---------------- launch ----------------
extern "C" void kernel_launch(void* const* d_in, const int* in_sizes, int n_in,
                              void* d_out, int out_size)
{
    const float* x  = (const float*)d_in[0];
    const int*   ei = (const int*)d_in[1];
    const float* W1 = (const float*)d_in[2];
    const float* b1 = (const float*)d_in[3];
    const float* W2 = (const float*)d_in[4];
    const float* b2 = (const float*)d_in[5];
    const float* W3 = (const float*)d_in[6];
    const float* b3 = (const float*)d_in[7];
    float* out = (float*)d_out;

    float *pH, *pHB, *pC16;
    __nv_bfloat16 *pW1P, *pW2P;
    cudaGetSymbolAddress((void**)&pH,   g_h);
    cudaGetSymbolAddress((void**)&pHB,  g_hb);
    cudaGetSymbolAddress((void**)&pC16, g_c16);
    cudaGetSymbolAddress((void**)&pW1P, g_w1p);
    cudaGetSymbolAddress((void**)&pW2P, g_w2p);

    // one-time setup (host objects only; no device memory)
    static cudaStream_t s1 = nullptr;
    static cudaEvent_t  e0 = nullptr, e1 = nullptr;
    if (!s1) {
        cudaFuncSetAttribute(fgemm128<256>, cudaFuncAttributeMaxDynamicSharedMemorySize, FGEMM_SMEM);
        cudaFuncSetAttribute(fgemm128<128>, cudaFuncAttributeMaxDynamicSharedMemorySize, FGEMM_SMEM);
        cudaStreamCreateWithFlags(&s1, cudaStreamNonBlocking);
        cudaEventCreateWithFlags(&e0, cudaEventDisableTiming);
        cudaEventCreateWithFlags(&e1, cudaEventDisableTiming);
    }

    const int* e_src = ei;
    const int* e_dst = ei + EE;

    const int AGG_BLOCKS  = (NN + 7) / 8;
    const int GEMM_BLOCKS = MPAD / 128;  // 782

    // Fork: CSR build + W2 split on s1, concurrent with W1 split + fgemm1 on stream 0.
    cudaEventRecord(e0, 0);
    cudaStreamWaitEvent(s1, e0, 0);

    // s1: CSR chain (L2-atomic/DRAM bound)
    k_zero_counts<<<(NN + 255) / 256, 256, 0, s1>>>();
    k_hist<<<(EE / 4 + 255) / 256, 256, 0, s1>>>(e_dst);
    k_scan_part<<<NBLK, 256, 0, s1>>>();
    k_scan_top<<<1, 512, 0, s1>>>();
    k_scan_write<<<NBLK, 256, 0, s1>>>();
    k_scatter<<<(EE / 4 + 255) / 256, 256, 0, s1>>>(e_src, e_dst);
    k_split_w<<<(128 * 32 + 255) / 256, 256, 0, s1>>>(W2, pW2P, 128);
    cudaEventRecord(e1, s1);

    // stream 0: W1 split + layer-1 GEMM (tensor bound)
    k_split_w<<<(256 * 32 + 255) / 256, 256>>>(W1, pW1P, 256);
    fgemm128<256><<<GEMM_BLOCKS, 256, FGEMM_SMEM>>>(x, pW1P, pH, NN);

    // join: aggregation needs both CSR and GEMM output
    cudaStreamWaitEvent(0, e1, 0);

    // Layer 1 aggregation
    agg128<true><<<AGG_BLOCKS, 256>>>((const float4*)pH, b1, (float4*)pHB);

    // Layer 2
    fgemm128<128><<<GEMM_BLOCKS, 256, FGEMM_SMEM>>>(pHB, pW2P, pH, NN);
    agg128<true><<<AGG_BLOCKS, 256>>>((const float4*)pH, b2, (float4*)pHB);

    // Layer 3
    gemm16<<<(NN + 63) / 64, 256>>>(pHB, W3, pC16, NN);
    agg16<<<AGG_BLOCKS, 256>>>(pC16, b3, out);
}

// round 8
// speedup vs baseline: 1.9244x; 1.0674x over previous
#include <cuda_runtime.h>
#include <cuda_bf16.h>
#include <cuda_pipeline.h>
#include <cstdint>

#define NN 100000
#define EE 1600000
#define MPAD 100096   // 782 * 128
#define NBLK 391      // ceil(NN/256)

// ---------------- scratch ----------------
__device__ int   g_counts[NN];
__device__ int   g_bsum[NBLK];
__device__ int   g_boff[NBLK];
__device__ int   g_row[NN + 1];
__device__ int   g_cursor[NN];
__device__ float g_dinv[NN];
__device__ int   g_csrc[EE];

__device__ float g_h[(size_t)MPAD * 128];   // GEMM out (agg input)
__device__ float g_hb[(size_t)MPAD * 128];  // agg out (next GEMM input); rows >= NN stay 0
__device__ float g_c16[(size_t)MPAD * 16];
__device__ __nv_bfloat16 g_w1p[512 * 128];  // [W1h ; W1l]
__device__ __nv_bfloat16 g_w2p[256 * 128];  // [W2h ; W2l]

// ---------------- helpers ----------------
__device__ __forceinline__ uint32_t smem_to_u32(const void* p) {
    uint32_t a;
    asm("{ .reg .u64 t; cvta.to.shared.u64 t, %1; cvt.u32.u64 %0, t; }" : "=r"(a) : "l"(p));
    return a;
}

__device__ __forceinline__ void split4(float4 v, uint2& hi, uint2& lo) {
    __align__(8) __nv_bfloat16 h[4], l[4];
    float f[4] = {v.x, v.y, v.z, v.w};
#pragma unroll
    for (int i = 0; i < 4; i++) {
        h[i] = __float2bfloat16_rn(f[i]);
        l[i] = __float2bfloat16_rn(f[i] - __bfloat162float(h[i]));
    }
    hi = *(uint2*)h;
    lo = *(uint2*)l;
}

// split a float2 into packed bf16x2 hi and lo (low half = .x, high half = .y)
__device__ __forceinline__ void split2(float2 v, uint32_t& h, uint32_t& l) {
    __nv_bfloat16 h0 = __float2bfloat16_rn(v.x), h1 = __float2bfloat16_rn(v.y);
    float r0 = v.x - __bfloat162float(h0), r1 = v.y - __bfloat162float(h1);
    __nv_bfloat16 l0 = __float2bfloat16_rn(r0), l1 = __float2bfloat16_rn(r1);
    h = ((uint32_t)__bfloat16_as_ushort(h1) << 16) | (uint32_t)__bfloat16_as_ushort(h0);
    l = ((uint32_t)__bfloat16_as_ushort(l1) << 16) | (uint32_t)__bfloat16_as_ushort(l0);
}

__device__ __forceinline__ void ldsm_x4_t(uint32_t& r0, uint32_t& r1, uint32_t& r2, uint32_t& r3,
                                          uint32_t addr) {
    asm volatile("ldmatrix.sync.aligned.m8n8.x4.trans.shared.b16 {%0,%1,%2,%3}, [%4];"
                 : "=r"(r0), "=r"(r1), "=r"(r2), "=r"(r3) : "r"(addr));
}

__device__ __forceinline__ void mma_16816(float* c, const uint32_t* a, const uint32_t* b) {
    asm volatile(
        "mma.sync.aligned.m16n8k16.row.col.f32.bf16.bf16.f32 "
        "{%0,%1,%2,%3}, {%4,%5,%6,%7}, {%8,%9}, {%0,%1,%2,%3};"
        : "+f"(c[0]), "+f"(c[1]), "+f"(c[2]), "+f"(c[3])
        : "r"(a[0]), "r"(a[1]), "r"(a[2]), "r"(a[3]), "r"(b[0]), "r"(b[1]));
}

// W[K,128] -> WP[2K,128] = [Wh ; Wl]
__global__ void k_split_w(const float* __restrict__ W, __nv_bfloat16* __restrict__ WP, int K) {
    int i = blockIdx.x * blockDim.x + threadIdx.x;
    if (i >= K * 32) return;
    int row = i >> 5, c4 = (i & 31) * 4;
    float4 v = ((const float4*)W)[i];
    uint2 h, l; split4(v, h, l);
    *(uint2*)(WP + (size_t)row * 128 + c4)       = h;
    *(uint2*)(WP + (size_t)(K + row) * 128 + c4) = l;
}

// ---------------- CSR build ----------------
__global__ void k_zero_counts() {
    int i = blockIdx.x * blockDim.x + threadIdx.x;
    if (i < NN) g_counts[i] = 0;
}

__global__ void k_hist(const int* __restrict__ dst) {
    int i = blockIdx.x * blockDim.x + threadIdx.x;
    if (i < EE / 4) {
        int4 d = ((const int4*)dst)[i];
        atomicAdd(&g_counts[d.x], 1);
        atomicAdd(&g_counts[d.y], 1);
        atomicAdd(&g_counts[d.z], 1);
        atomicAdd(&g_counts[d.w], 1);
    }
}

__global__ void k_scan_part() {
    __shared__ int sm[256];
    int i = blockIdx.x * 256 + threadIdx.x;
    sm[threadIdx.x] = (i < NN) ? g_counts[i] : 0;
    __syncthreads();
#pragma unroll
    for (int off = 128; off > 0; off >>= 1) {
        if (threadIdx.x < off) sm[threadIdx.x] += sm[threadIdx.x + off];
        __syncthreads();
    }
    if (threadIdx.x == 0) g_bsum[blockIdx.x] = sm[0];
}

__global__ void k_scan_top() {
    __shared__ int sm[512];
    int t = threadIdx.x;
    sm[t] = (t < NBLK) ? g_bsum[t] : 0;
    __syncthreads();
    for (int off = 1; off < 512; off <<= 1) {
        int v = (t >= off) ? sm[t - off] : 0;
        __syncthreads();
        sm[t] += v;
        __syncthreads();
    }
    if (t < NBLK) g_boff[t] = (t == 0) ? 0 : sm[t - 1];
}

__global__ void k_scan_write() {
    int b = blockIdx.x, t = threadIdx.x;
    int i = b * 256 + t;
    int c = (i < NN) ? g_counts[i] : 0;
    int lane = t & 31, w = t >> 5;
    int v = c;
#pragma unroll
    for (int off = 1; off < 32; off <<= 1) {
        int u = __shfl_up_sync(0xffffffffu, v, off);
        if (lane >= off) v += u;
    }
    __shared__ int wsum[8];
    if (lane == 31) wsum[w] = v;
    __syncthreads();
    if (w == 0) {
        int x = (lane < 8) ? wsum[lane] : 0;
#pragma unroll
        for (int off = 1; off < 8; off <<= 1) {
            int u = __shfl_up_sync(0xffffffffu, x, off);
            if (lane >= off) x += u;
        }
        if (lane < 8) wsum[lane] = x;
    }
    __syncthreads();
    int excl = v - c + ((w > 0) ? wsum[w - 1] : 0) + g_boff[b];
    if (i < NN) {
        g_row[i]    = excl;
        g_cursor[i] = excl;
        g_dinv[i]   = rsqrtf((float)(c + 1));
    }
    if (i == NN - 1) g_row[NN] = excl + c;
}

__global__ void k_scatter(const int* __restrict__ src, const int* __restrict__ dst) {
    int i = blockIdx.x * blockDim.x + threadIdx.x;
    if (i < EE / 4) {
        int4 s = ((const int4*)src)[i];
        int4 d = ((const int4*)dst)[i];
        int p;
        p = atomicAdd(&g_cursor[d.x], 1); g_csrc[p] = s.x;
        p = atomicAdd(&g_cursor[d.y], 1); g_csrc[p] = s.y;
        p = atomicAdd(&g_cursor[d.z], 1); g_csrc[p] = s.z;
        p = atomicAdd(&g_cursor[d.w], 1); g_csrc[p] = s.w;
    }
}

// ---------------- raw-mma fused-split GEMM: C[.,128] = A_fp32[.,K] * W[K,128] ----------------
// A fragments built directly in registers (LDG fp32 -> split bf16 hi/lo -> pack).
// B (WP=[Wh;Wl]) double-buffered k32 chunks in smem, fragments via ldmatrix.x4.trans.
// C = ah*Wh + al*Wh + ah*Wl, fp32 accumulate. Warp tile: 16 rows x 128 cols.
template <int K>
__global__ __launch_bounds__(256, 2) void fgemm_mma(
    const float* __restrict__ A, const __nv_bfloat16* __restrict__ WP,
    float* __restrict__ C, int M)
{
    constexpr int NCH  = K / 32;        // k32 chunks
    constexpr int LDBB = 272;           // bytes per B smem row (256B data + 16B pad)
    constexpr int HALF = 32 * LDBB;     // 8704 B (one half: hi or lo)
    constexpr int STAGE = 2 * HALF;     // 17408 B

    __shared__ __align__(16) char sB[2 * STAGE];   // 34816 B

    const int tid  = threadIdx.x;
    const int warp = tid >> 5;
    const int lane = tid & 31;
    const int m0   = warp * 16;
    const size_t rowBase = (size_t)blockIdx.x * 128;
    const uint32_t sbase = smem_to_u32(sB);

    auto issueB = [&](int ch) {
        int st = ch & 1, k0 = ch * 32;
#pragma unroll
        for (int rep = 0; rep < 4; rep++) {
            int idx  = tid + rep * 256;       // 0..1023
            int half = idx >> 9;              // 0=hi, 1=lo
            int r    = (idx >> 4) & 31;
            int c16  = idx & 15;
            __pipeline_memcpy_async(
                sB + st * STAGE + half * HALF + r * LDBB + c16 * 16,
                (const char*)WP + ((size_t)(half * K + k0 + r) * 256 + c16 * 16), 16);
        }
    };

    // A staging (fp32 for one k16 frag), loaded exactly in mma fragment ownership
    const int rlo  = lane >> 2;          // 0..7
    const int tcol = (lane & 3) * 2;     // 0,2,4,6
    float2 p0, p1, p2, p3;
    auto ldA = [&](int g) {              // g = global k16 index
        int k = g * 16 + tcol;
        size_t ra = rowBase + m0 + rlo;
        size_t rb = ra + 8;
        p0 = (ra < (size_t)M) ? *(const float2*)&A[ra * K + k]     : make_float2(0.f, 0.f);
        p1 = (rb < (size_t)M) ? *(const float2*)&A[rb * K + k]     : make_float2(0.f, 0.f);
        p2 = (ra < (size_t)M) ? *(const float2*)&A[ra * K + k + 8] : make_float2(0.f, 0.f);
        p3 = (rb < (size_t)M) ? *(const float2*)&A[rb * K + k + 8] : make_float2(0.f, 0.f);
    };

    float c[16][4];
#pragma unroll
    for (int i = 0; i < 16; i++)
#pragma unroll
        for (int j = 0; j < 4; j++) c[i][j] = 0.f;

    issueB(0);
    __pipeline_commit();
    ldA(0);

    // per-lane ldmatrix row/col within a k16 x n16 tile group
    const int krow  = (lane & 7) + ((lane >> 3) & 1) * 8;  // tile row
    const int nside = ((lane >> 4) & 1) * 8;               // 0 or 8 (n offset)

    for (int ch = 0; ch < NCH; ch++) {
        int st = ch & 1;
        __pipeline_wait_prior(0);     // B chunk ch resident
        __syncthreads();              // everyone past chunk ch-1's reads
        if (ch + 1 < NCH) { issueB(ch + 1); __pipeline_commit(); }

#pragma unroll
        for (int h16 = 0; h16 < 2; h16++) {
            uint32_t ah[4], al[4];
            split2(p0, ah[0], al[0]);
            split2(p1, ah[1], al[1]);
            split2(p2, ah[2], al[2]);
            split2(p3, ah[3], al[3]);
            int g = ch * 2 + h16;
            if (g + 1 < K / 16) ldA(g + 1);   // prefetch; latency hides under mma

            uint32_t bh_base = sbase + st * STAGE + (h16 * 16 + krow) * LDBB + nside * 2;
            uint32_t bl_base = bh_base + HALF;
#pragma unroll
            for (int grp = 0; grp < 8; grp++) {   // n16 groups: cols grp*16..+15
                uint32_t h0, h1, h2, h3, l0, l1, l2, l3;
                ldsm_x4_t(h0, h1, h2, h3, bh_base + grp * 32);
                ldsm_x4_t(l0, l1, l2, l3, bl_base + grp * 32);
                uint32_t bA[2] = {h0, h1}, bB[2] = {h2, h3};
                uint32_t lA[2] = {l0, l1}, lB[2] = {l2, l3};
                mma_16816(c[grp * 2],     ah, bA);
                mma_16816(c[grp * 2],     al, bA);
                mma_16816(c[grp * 2],     ah, lA);
                mma_16816(c[grp * 2 + 1], ah, bB);
                mma_16816(c[grp * 2 + 1], al, bB);
                mma_16816(c[grp * 2 + 1], ah, lB);
            }
        }
    }

    // epilogue: direct STG (C is padded to MPAD rows; no guard needed)
    size_t ra = rowBase + m0 + rlo;
#pragma unroll
    for (int n8 = 0; n8 < 16; n8++) {
        int col = n8 * 8 + tcol;
        *(float2*)&C[ra * 128 + col]       = make_float2(c[n8][0], c[n8][1]);
        *(float2*)&C[(ra + 8) * 128 + col] = make_float2(c[n8][2], c[n8][3]);
    }
}

// ---------------- small GEMM: C[M,16] = A[M,128] * W[128,16] ----------------
__global__ __launch_bounds__(256) void gemm16(
    const float* __restrict__ A, const float* __restrict__ W,
    float* __restrict__ C, int M)
{
    __shared__ float xs[64][132];
    __shared__ float ws[128][16];

    int tid = threadIdx.x;
    int r0 = blockIdx.x * 64;

    for (int i = tid; i < 2048; i += 256) {
        int row = i >> 5;
        int c4 = i & 31;
        int gr = r0 + row;
        float4 v = (gr < M) ? *(const float4*)(A + (size_t)gr * 128 + c4 * 4)
                            : make_float4(0.f, 0.f, 0.f, 0.f);
        *(float4*)(&xs[row][c4 * 4]) = v;
    }
    for (int i = tid; i < 2048; i += 256) ws[i >> 4][i & 15] = W[i];
    __syncthreads();

    int col = tid & 15;
    int rq  = tid >> 4;
    float acc[4] = {0.f, 0.f, 0.f, 0.f};
    for (int k = 0; k < 128; k++) {
        float w = ws[k][col];
#pragma unroll
        for (int r = 0; r < 4; r++)
            acc[r] = fmaf(xs[rq * 4 + r][k], w, acc[r]);
    }
#pragma unroll
    for (int r = 0; r < 4; r++) {
        int gr = r0 + rq * 4 + r;
        if (gr < M) C[(size_t)gr * 16 + col] = acc[r];
    }
}

// ---------------- aggregation, F=128 ----------------
template <bool RELU>
__global__ __launch_bounds__(256) void agg128(
    const float4* __restrict__ h, const float* __restrict__ bias,
    float4* __restrict__ outF)
{
    int warp = (blockIdx.x * blockDim.x + threadIdx.x) >> 5;
    int lane = threadIdx.x & 31;
    if (warp >= NN) return;
    int v = warp;

    float dv = g_dinv[v];
    float4 self = h[(size_t)v * 32 + lane];
    float4 acc;
    acc.x = dv * self.x; acc.y = dv * self.y;
    acc.z = dv * self.z; acc.w = dv * self.w;

    int rs = g_row[v], re = g_row[v + 1];
    int base = rs;
    for (; base + 32 <= re; base += 32) {
        int   s = g_csrc[base + lane];
        float d = g_dinv[s];
#pragma unroll
        for (int j = 0; j < 32; j++) {
            int   sj = __shfl_sync(0xffffffffu, s, j);
            float dj = __shfl_sync(0xffffffffu, d, j);
            float4 hv = h[(size_t)sj * 32 + lane];
            acc.x = fmaf(dj, hv.x, acc.x);
            acc.y = fmaf(dj, hv.y, acc.y);
            acc.z = fmaf(dj, hv.z, acc.z);
            acc.w = fmaf(dj, hv.w, acc.w);
        }
    }
    if (base < re) {
        int cnt = re - base;
        int   s = (lane < cnt) ? g_csrc[base + lane] : 0;
        float d = (lane < cnt) ? g_dinv[s] : 0.f;
        for (int j = 0; j < cnt; j++) {
            int   sj = __shfl_sync(0xffffffffu, s, j);
            float dj = __shfl_sync(0xffffffffu, d, j);
            float4 hv = h[(size_t)sj * 32 + lane];
            acc.x = fmaf(dj, hv.x, acc.x);
            acc.y = fmaf(dj, hv.y, acc.y);
            acc.z = fmaf(dj, hv.z, acc.z);
            acc.w = fmaf(dj, hv.w, acc.w);
        }
    }

    float4 bb = *(const float4*)(bias + 4 * lane);
    acc.x = fmaf(acc.x, dv, bb.x);
    acc.y = fmaf(acc.y, dv, bb.y);
    acc.z = fmaf(acc.z, dv, bb.z);
    acc.w = fmaf(acc.w, dv, bb.w);
    if (RELU) {
        acc.x = fmaxf(acc.x, 0.f); acc.y = fmaxf(acc.y, 0.f);
        acc.z = fmaxf(acc.z, 0.f); acc.w = fmaxf(acc.w, 0.f);
    }
    outF[(size_t)v * 32 + lane] = acc;
}

// ---------------- aggregation, F=16 ----------------
__global__ __launch_bounds__(256) void agg16(
    const float* __restrict__ h, const float* __restrict__ bias,
    float* __restrict__ out)
{
    int warp = (blockIdx.x * blockDim.x + threadIdx.x) >> 5;
    int lane = threadIdx.x & 31;
    if (warp >= NN) return;
    int v = warp;

    float dv = g_dinv[v];
    float acc = (lane < 16) ? dv * h[(size_t)v * 16 + lane] : 0.f;

    int rs = g_row[v], re = g_row[v + 1];
    int base = rs;
    for (; base + 32 <= re; base += 32) {
        int   s = g_csrc[base + lane];
        float d = g_dinv[s];
#pragma unroll
        for (int j = 0; j < 32; j++) {
            int   sj = __shfl_sync(0xffffffffu, s, j);
            float dj = __shfl_sync(0xffffffffu, d, j);
            if (lane < 16) acc = fmaf(dj, h[(size_t)sj * 16 + lane], acc);
        }
    }
    if (base < re) {
        int cnt = re - base;
        int   s = (lane < cnt) ? g_csrc[base + lane] : 0;
        float d = (lane < cnt) ? g_dinv[s] : 0.f;
        for (int j = 0; j < cnt; j++) {
            int   sj = __shfl_sync(0xffffffffu, s, j);
            float dj = __shfl_sync(0xffffffffu, d, j);
            if (lane < 16) acc = fmaf(dj, h[(size_t)sj * 16 + lane], acc);
        }
    }

    if (lane < 16) {
        acc = fmaf(acc, dv, bias[lane]);
        out[(size_t)v * 16 + lane] = acc;
    }
}

// ---------------- launch ----------------
extern "C" void kernel_launch(void* const* d_in, const int* in_sizes, int n_in,
                              void* d_out, int out_size)
{
    const float* x  = (const float*)d_in[0];
    const int*   ei = (const int*)d_in[1];
    const float* W1 = (const float*)d_in[2];
    const float* b1 = (const float*)d_in[3];
    const float* W2 = (const float*)d_in[4];
    const float* b2 = (const float*)d_in[5];
    const float* W3 = (const float*)d_in[6];
    const float* b3 = (const float*)d_in[7];
    float* out = (float*)d_out;

    float *pH, *pHB, *pC16;
    __nv_bfloat16 *pW1P, *pW2P;
    cudaGetSymbolAddress((void**)&pH,   g_h);
    cudaGetSymbolAddress((void**)&pHB,  g_hb);
    cudaGetSymbolAddress((void**)&pC16, g_c16);
    cudaGetSymbolAddress((void**)&pW1P, g_w1p);
    cudaGetSymbolAddress((void**)&pW2P, g_w2p);

    static cudaStream_t s1 = nullptr;
    static cudaEvent_t  e0 = nullptr, e1 = nullptr;
    if (!s1) {
        cudaStreamCreateWithFlags(&s1, cudaStreamNonBlocking);
        cudaEventCreateWithFlags(&e0, cudaEventDisableTiming);
        cudaEventCreateWithFlags(&e1, cudaEventDisableTiming);
    }

    const int* e_src = ei;
    const int* e_dst = ei + EE;

    const int AGG_BLOCKS  = (NN + 7) / 8;
    const int GEMM_BLOCKS = MPAD / 128;  // 782

    // Fork: CSR chain + W2 split on s1, concurrent with W1 split + fgemm1 on stream 0.
    cudaEventRecord(e0, 0);
    cudaStreamWaitEvent(s1, e0, 0);

    k_zero_counts<<<(NN + 255) / 256, 256, 0, s1>>>();
    k_hist<<<(EE / 4 + 255) / 256, 256, 0, s1>>>(e_dst);
    k_scan_part<<<NBLK, 256, 0, s1>>>();
    k_scan_top<<<1, 512, 0, s1>>>();
    k_scan_write<<<NBLK, 256, 0, s1>>>();
    k_scatter<<<(EE / 4 + 255) / 256, 256, 0, s1>>>(e_src, e_dst);
    k_split_w<<<(128 * 32 + 255) / 256, 256, 0, s1>>>(W2, pW2P, 128);
    cudaEventRecord(e1, s1);

    // stream 0: W1 split + layer-1 GEMM (raw mma tensor path)
    k_split_w<<<(256 * 32 + 255) / 256, 256>>>(W1, pW1P, 256);
    fgemm_mma<256><<<GEMM_BLOCKS, 256>>>(x, pW1P, pH, NN);

    cudaStreamWaitEvent(0, e1, 0);

    // Layer 1 aggregation
    agg128<true><<<AGG_BLOCKS, 256>>>((const float4*)pH, b1, (float4*)pHB);

    // Layer 2 (g_hb rows >= NN are never written -> zero-init -> safe unguarded A reads)
    fgemm_mma<128><<<GEMM_BLOCKS, 256>>>(pHB, pW2P, pH, MPAD);
    agg128<true><<<AGG_BLOCKS, 256>>>((const float4*)pH, b2, (float4*)pHB);

    // Layer 3
    gemm16<<<(NN + 63) / 64, 256>>>(pHB, W3, pC16, NN);
    agg16<<<AGG_BLOCKS, 256>>>(pC16, b3, out);
}